// round 12
// baseline (speedup 1.0000x reference)
#include <cuda_runtime.h>
#include <cuda_bf16.h>
#include <cstdint>
#include <cstddef>

#define BSZ 32
#define TSZ 2048
#define DSZ 512
#define NSZ 512
#define MROWS (BSZ * TSZ)      // 65536
#define NCAT  (4 * NSZ)        // 2048

// ---------------- device scratch (allocation-free: __device__ globals) -------
__device__ float  g_G[(size_t)TSZ * BSZ * NCAT];         // 512 MB  [t][b][gate*512+n]
__device__ __nv_bfloat16 g_Ahi[(size_t)MROWS * DSZ];     // 64 MB (x, then h history)
__device__ __nv_bfloat16 g_Alo[(size_t)MROWS * DSZ];     // 64 MB
__device__ __nv_bfloat16 g_Bhi[(size_t)NCAT * DSZ];      // 2 MB   [n][k] (W^T)
__device__ __nv_bfloat16 g_Blo[(size_t)NCAT * DSZ];      // 2 MB
__device__ __nv_bfloat16 g_UThi[(size_t)NCAT * DSZ];     // 2 MB   [n*4+gate][k]
__device__ __nv_bfloat16 g_UTlo[(size_t)NCAT * DSZ];     // 2 MB
__device__ float  g_biascat[NCAT];
__device__ int    g_pcnt[16 * 32];                       // (bg,sg) counters, 128B apart
__device__ int    g_pflag[16 * 32];                      // (bg,ks) flags

// ---------------- PTX helpers (baseline PTX: sm_80+ features only) ----------
__device__ __forceinline__ uint32_t smem_to_u32(const void* p) {
    uint32_t a;
    asm("{ .reg .u64 t; cvta.to.shared.u64 t, %1; cvt.u32.u64 %0, t; }" : "=r"(a) : "l"(p));
    return a;
}
#define CP_ASYNC16(dst, src) \
    asm volatile("cp.async.cg.shared.global [%0], [%1], 16;" :: "r"(dst), "l"(src))
#define CP_COMMIT() asm volatile("cp.async.commit_group;" ::: "memory")
#define CP_WAIT(n)  asm volatile("cp.async.wait_group %0;" :: "n"(n) : "memory")

__device__ __forceinline__ void ldsm_x4(uint32_t* r, uint32_t addr) {
    asm volatile("ldmatrix.sync.aligned.m8n8.x4.shared.b16 {%0,%1,%2,%3}, [%4];"
                 : "=r"(r[0]), "=r"(r[1]), "=r"(r[2]), "=r"(r[3]) : "r"(addr));
}
__device__ __forceinline__ void ldsm_x2(uint32_t* r, uint32_t addr) {
    asm volatile("ldmatrix.sync.aligned.m8n8.x2.shared.b16 {%0,%1}, [%2];"
                 : "=r"(r[0]), "=r"(r[1]) : "r"(addr));
}
__device__ __forceinline__ void mma16816(float* c, const uint32_t* a, const uint32_t* b) {
    asm volatile("mma.sync.aligned.m16n8k16.row.col.f32.bf16.bf16.f32 "
                 "{%0,%1,%2,%3}, {%4,%5,%6,%7}, {%8,%9}, {%0,%1,%2,%3};"
                 : "+f"(c[0]), "+f"(c[1]), "+f"(c[2]), "+f"(c[3])
                 : "r"(a[0]), "r"(a[1]), "r"(a[2]), "r"(a[3]), "r"(b[0]), "r"(b[1]));
}
__device__ __forceinline__ int ld_acq(const int* p) {
    int v;
    asm volatile("ld.acquire.gpu.global.b32 %0, [%1];" : "=r"(v) : "l"(p) : "memory");
    return v;
}
__device__ __forceinline__ void st_rel(int* p, int v) {
    asm volatile("st.release.gpu.global.b32 [%0], %1;" :: "l"(p), "r"(v) : "memory");
}

// ---------------- conversion helpers -----------------------------------------
__device__ __forceinline__ unsigned bf16pack2(float a, float b)
{
    return (unsigned)__bfloat16_as_ushort(__float2bfloat16(a)) |
           ((unsigned)__bfloat16_as_ushort(__float2bfloat16(b)) << 16);
}
__device__ __forceinline__ float bf16res(float a)
{
    return a - __bfloat162float(__float2bfloat16(a));
}

// ---------------- launch 0: x -> bf16 hi/lo ----------------------------------
__global__ void cvt_x_kernel(const float* __restrict__ src)
{
    size_t i = (size_t)blockIdx.x * 256 + threadIdx.x;
    float4 v = ((const float4*)src)[i];
    uint2 ph, pl;
    ph.x = bf16pack2(v.x, v.y);
    ph.y = bf16pack2(v.z, v.w);
    pl.x = bf16pack2(bf16res(v.x), bf16res(v.y));
    pl.y = bf16pack2(bf16res(v.z), bf16res(v.w));
    ((uint2*)g_Ahi)[i] = ph;
    ((uint2*)g_Alo)[i] = pl;
}

// ---------------- launch 1: mega-prep ----------------------------------------
__global__ void prep_all_kernel(
    const float* __restrict__ W0, const float* __restrict__ W1,
    const float* __restrict__ W2, const float* __restrict__ W3,
    const float* __restrict__ U0, const float* __restrict__ U1,
    const float* __restrict__ U2, const float* __restrict__ U3,
    const float* __restrict__ bi, const float* __restrict__ bf,
    const float* __restrict__ bg, const float* __restrict__ bc)
{
    __shared__ float t[32][33];
    const int bx  = blockIdx.x;
    const int tid = threadIdx.x;
    const int tx  = tid & 31;
    const int ty  = tid >> 5;

    if (bx < 1024) {
        int z = bx >> 8, rem = bx & 255;
        const float* W = (z == 0) ? W0 : (z == 1) ? W1 : (z == 2) ? W2 : W3;
        int n0 = (rem & 15) * 32, k0 = (rem >> 4) * 32;
#pragma unroll
        for (int r = 0; r < 32; r += 8)
            t[ty + r][tx] = W[(size_t)(k0 + ty + r) * NSZ + n0 + tx];
        __syncthreads();
#pragma unroll
        for (int r = 0; r < 32; r += 8) {
            float v = t[tx][ty + r];
            size_t o = (size_t)(z * NSZ + n0 + ty + r) * DSZ + k0 + tx;
            g_Bhi[o] = __float2bfloat16(v);
            g_Blo[o] = __float2bfloat16(bf16res(v));
        }
    } else if (bx < 2048) {
        int idx = bx - 1024;
        int z = idx >> 8, rem = idx & 255;
        const float* U = (z == 0) ? U0 : (z == 1) ? U1 : (z == 2) ? U2 : U3;
        int n0 = (rem & 15) * 32, k0 = (rem >> 4) * 32;
#pragma unroll
        for (int r = 0; r < 32; r += 8)
            t[ty + r][tx] = U[(size_t)(k0 + ty + r) * NSZ + n0 + tx];
        __syncthreads();
#pragma unroll
        for (int r = 0; r < 32; r += 8) {
            float v = t[tx][ty + r];
            size_t o = ((size_t)(n0 + ty + r) * 4 + z) * DSZ + k0 + tx;
            g_UThi[o] = __float2bfloat16(v);
            g_UTlo[o] = __float2bfloat16(bf16res(v));
        }
    } else if (bx < 2050) {
        int i = (bx - 2048) * 256 + tid;
        g_biascat[i]           = bi[i];
        g_biascat[NSZ + i]     = bf[i];
        g_biascat[2 * NSZ + i] = bg[i];
        g_biascat[3 * NSZ + i] = bc[i];
    } else if (bx < 2054) {
        int i = (bx - 2050) * 256 + tid;           // 0..1023
        if (i < 512)       g_pcnt[i] = 0;
        else               g_pflag[i - 512] = 0;
    }
}

__global__ void wtrans_kernel(const float* __restrict__ W, int rowbase)
{
    __shared__ float t[32][33];
    int tx = threadIdx.x, ty = threadIdx.y;
    int n0 = blockIdx.x * 32, k0 = blockIdx.y * 32;
#pragma unroll
    for (int r = 0; r < 32; r += 8)
        t[ty + r][tx] = W[(size_t)(k0 + ty + r) * NSZ + n0 + tx];
    __syncthreads();
#pragma unroll
    for (int r = 0; r < 32; r += 8) {
        float v = t[tx][ty + r];
        size_t o = (size_t)(rowbase + n0 + ty + r) * DSZ + k0 + tx;
        g_Bhi[o] = __float2bfloat16(v);
        g_Blo[o] = __float2bfloat16(bf16res(v));
    }
}

// ---------------- HMMA GEMM (unchanged) --------------------------------------
#define GSM_TOTAL (2 * 65536)

__global__ __launch_bounds__(256, 1) void gemm_mma_kernel(
    const float* __restrict__ bias_ext, float* __restrict__ out_ext, int mode)
{
    extern __shared__ char smem[];
    const uint32_t smem_base = smem_to_u32(smem);
    const int tid  = threadIdx.x;
    const int wid  = tid >> 5;
    const int lane = tid & 31;
    const int wm   = wid & 1;
    const int wn   = wid >> 1;
    const int mbase = blockIdx.y * 128;
    const int nbase = blockIdx.x * 128;

    uint32_t dsts[16];
#pragma unroll
    for (int v = 0; v < 16; v++) {
        int row = (v & 3) * 32 + (tid >> 3);
        uint32_t off = row * 128 + (tid & 7) * 16;
        dsts[v] = (uint32_t)((v >> 2) * 16384) + (off ^ ((off >> 3) & 0x70));
    }

#define ISSUE_CHUNK(KT, BUFOFF) do {                                                 \
    int _kt = (KT);                                                                  \
    uint32_t _bo = (BUFOFF);                                                         \
    _Pragma("unroll")                                                                \
    for (int v = 0; v < 16; v++) {                                                   \
        const __nv_bfloat16* bp = (v < 4) ? g_Ahi : (v < 8) ? g_Alo                  \
                                  : (v < 12) ? g_Bhi : g_Blo;                        \
        int rb = (v < 8) ? mbase : nbase;                                            \
        int row = (v & 3) * 32 + (tid >> 3);                                         \
        CP_ASYNC16(smem_base + _bo + dsts[v],                                        \
                   bp + ((size_t)(rb + row) << 9) + _kt + ((tid & 7) << 3));         \
    }                                                                                \
    CP_COMMIT();                                                                     \
} while (0)

    uint32_t a_rowoff[4], a_swz[4];
#pragma unroll
    for (int mf = 0; mf < 4; mf++) {
        int row = wm * 64 + mf * 16 + (lane & 15);
        a_rowoff[mf] = row * 128;
        a_swz[mf]    = (row & 7) << 4;
    }
    const uint32_t a_cb = (uint32_t)(lane >> 4) * 16;
    uint32_t b_rowoff[4], b_swz[4];
#pragma unroll
    for (int nf = 0; nf < 4; nf++) {
        int row = wn * 32 + nf * 8 + (lane & 7);
        b_rowoff[nf] = row * 128;
        b_swz[nf]    = (row & 7) << 4;
    }
    const uint32_t b_cb = (uint32_t)((lane >> 3) & 1) * 16;

    float acc[4][4][4];
#pragma unroll
    for (int mf = 0; mf < 4; mf++)
#pragma unroll
        for (int nf = 0; nf < 4; nf++)
#pragma unroll
            for (int q = 0; q < 4; q++) acc[mf][nf][q] = 0.f;

    ISSUE_CHUNK(0, 0);

    for (int i = 0; i < 8; i++) {
        if (i < 7) {
            ISSUE_CHUNK((i + 1) * 64, (uint32_t)(((i + 1) & 1) * 65536));
            CP_WAIT(1);
        } else {
            CP_WAIT(0);
        }
        __syncthreads();

        const uint32_t base = smem_base + (uint32_t)((i & 1) * 65536);
#pragma unroll
        for (int k16 = 0; k16 < 4; k16++) {
            const uint32_t kb = (uint32_t)(k16 * 32);
            uint32_t aH[4][4], aL[4][4], bH[4][2], bL[4][2];
#pragma unroll
            for (int mf = 0; mf < 4; mf++) {
                uint32_t co = (kb + a_cb) ^ a_swz[mf];
                ldsm_x4(aH[mf], base + a_rowoff[mf] + co);
                ldsm_x4(aL[mf], base + 16384 + a_rowoff[mf] + co);
            }
#pragma unroll
            for (int nf = 0; nf < 4; nf++) {
                uint32_t co = (kb + b_cb) ^ b_swz[nf];
                ldsm_x2(bH[nf], base + 32768 + b_rowoff[nf] + co);
                ldsm_x2(bL[nf], base + 49152 + b_rowoff[nf] + co);
            }
#pragma unroll
            for (int mf = 0; mf < 4; mf++)
#pragma unroll
                for (int nf = 0; nf < 4; nf++) {
                    mma16816(acc[mf][nf], aH[mf], bH[nf]);
                    mma16816(acc[mf][nf], aH[mf], bL[nf]);
                    mma16816(acc[mf][nf], aL[mf], bH[nf]);
                }
        }
        __syncthreads();
    }

    const float* bias = mode ? bias_ext : g_biascat;
    float* C = mode ? out_ext : g_G;
    const int ncols = mode ? NSZ : NCAT;

#pragma unroll
    for (int mf = 0; mf < 4; mf++) {
#pragma unroll
        for (int h = 0; h < 2; h++) {
            int r = mbase + wm * 64 + mf * 16 + (lane >> 2) + h * 8;
            size_t crow;
            if (mode == 0) {
                int tt = r & (TSZ - 1), bb = r >> 11;
                crow = ((size_t)tt * BSZ + bb) * (size_t)ncols;
            } else {
                int tt = r >> 5, bb = r & 31;
                crow = ((size_t)bb * TSZ + tt) * (size_t)ncols;
            }
#pragma unroll
            for (int nf = 0; nf < 4; nf++) {
                int col = nbase + wn * 32 + nf * 8 + (lane & 3) * 2;
                float2 bv = *(const float2*)&bias[col];
                float2 o;
                o.x = acc[mf][nf][h * 2 + 0] + bv.x;
                o.y = acc[mf][nf][h * 2 + 1] + bv.y;
                if (mode) { o.x = fmaxf(o.x, 0.f); o.y = fmaxf(o.y, 0.f); }
                *(float2*)&C[crow + col] = o;
            }
        }
    }
#undef ISSUE_CHUNK
}

// ---------------- persistent MMA recurrence (sub-flag dataflow) --------------
// 128 CTAs = 4 batch-groups x 32 CTAs. CTA (bg, ci): batches [8bg,8bg+8),
// n-cols [16ci,16ci+16) -> UT rows [64ci,64ci+64). Warps: ks=wid&3, ms=wid>>2.
// Flags: one per (bg, k-chunk); producer subgroup sg=ci>>3, fan-in 8.
// h history lives directly in g_Ahi/g_Alo (rows (t*32+b)); no extra buffers.
#define SH 1040
#define RSM_HH 0
#define RSM_HL (8 * SH)
#define RSM_PART (16 * SH)
#define RSM_C (RSM_PART + 9216)
#define RSM_TOTAL (128 * SH)

__global__ __launch_bounds__(512, 1) void lstm_recur_mma()
{
    extern __shared__ char sm[];
    const uint32_t sb = smem_to_u32(sm);
    const int tid  = threadIdx.x;
    const int wid  = tid >> 5;
    const int lane = tid & 31;
    const int ks   = wid & 3;
    const int ms   = wid >> 2;
    const int cta  = blockIdx.x;
    const int bg   = cta >> 5;
    const int ci   = cta & 31;
    const int sg   = ci >> 3;

    // ---- one-time: stage UT slice (64 rows hi + 64 lo), build A-frags ----
#pragma unroll
    for (int q = 0; q < 16; q++) {
        int idx  = q * 512 + tid;
        int half = idx >> 12;
        int rem  = idx & 4095;
        int row  = rem >> 6, col = rem & 63;
        const __nv_bfloat16* src = half ? g_UTlo : g_UThi;
        CP_ASYNC16(sb + half * (64 * SH) + row * SH + col * 16,
                   src + ((size_t)(ci * 64 + row)) * DSZ + col * 8);
    }
    CP_COMMIT();
    CP_WAIT(0);
    __syncthreads();

    uint32_t aH[8][4], aL[8][4];
    {
        uint32_t rbase = sb + (ms * 16 + (lane & 15)) * SH + (lane >> 4) * 16;
#pragma unroll
        for (int j = 0; j < 8; j++) {
            uint32_t co = (uint32_t)(ks * 256 + j * 32);
            ldsm_x4(aH[j], rbase + co);
            ldsm_x4(aL[j], rbase + 64 * SH + co);
        }
    }
    __syncthreads();
    if (tid < 128) ((float*)(sm + RSM_C))[tid] = 0.f;
    __syncthreads();

    const int en = tid & 15;
    const int eb = tid >> 4;                   // valid for tid < 128

    float nxi = 0.f, nxf = 0.f, nxg = 0.f, nxc = 0.f;
    if (tid < 128) {
        size_t gb = (size_t)(bg * 8 + eb) * NCAT + (ci * 16 + en);
        nxi = __ldg(&g_G[gb]);
        nxf = __ldg(&g_G[gb + NSZ]);
        nxg = __ldg(&g_G[gb + 2 * NSZ]);
        nxc = __ldg(&g_G[gb + 3 * NSZ]);
    }

    const int lrow = lane >> 2;
    const uint32_t lcb = (uint32_t)(ks * 256 + (lane & 3) * 64);
    const uint32_t ldH = sb + RSM_HH + (uint32_t)lrow * SH + lcb;
    const uint32_t ldL = sb + RSM_HL + (uint32_t)lrow * SH + lcb;
    const uint32_t hbase = sb + (uint32_t)((lane & 7) * SH)
                         + (uint32_t)(((lane >> 3) & 1) * 16);

    int* cnt  = &g_pcnt[(bg * 4 + sg) * 32];   // producer-side counter
    int* wfl  = &g_pflag[(bg * 4 + sg) * 32];  // producer-side flag to release
    int* rfl  = &g_pflag[(bg * 4 + ks) * 32];  // consumer-side flag to poll

    for (int t = 0; t < TSZ; t++) {
        const float xi = nxi, xf = nxf, xg = nxg, xc = nxc;

        if (wid < 4) {
            if (t > 0) {
                if (lane == 0) { while (ld_acq(rfl) < t) {} }
                __syncwarp();
                const char* sH = (const char*)(g_Ahi
                    + ((size_t)(t - 1) * BSZ + bg * 8 + lrow) * NSZ) + lcb;
                const char* sL = (const char*)(g_Alo
                    + ((size_t)(t - 1) * BSZ + bg * 8 + lrow) * NSZ) + lcb;
#pragma unroll
                for (int i = 0; i < 4; i++) CP_ASYNC16(ldH + 16 * i, sH + 16 * i);
#pragma unroll
                for (int i = 0; i < 4; i++) CP_ASYNC16(ldL + 16 * i, sL + 16 * i);
                CP_COMMIT();
            }
            if (t + 1 < TSZ) {                 // prefetch G(t+1), overlaps loads
                size_t gb = ((size_t)(t + 1) * BSZ + bg * 8 + eb) * (size_t)NCAT
                          + (ci * 16 + en);
                nxi = __ldg(&g_G[gb]);
                nxf = __ldg(&g_G[gb + NSZ]);
                nxg = __ldg(&g_G[gb + 2 * NSZ]);
                nxc = __ldg(&g_G[gb + 3 * NSZ]);
            }
            if (t > 0) CP_WAIT(0);
        }
        if (t > 0) asm volatile("bar.sync %0, 128;" :: "r"(1 + ks));

        float acc[4] = {0.f, 0.f, 0.f, 0.f};
        if (t > 0) {
#pragma unroll
            for (int j = 0; j < 8; j++) {
                uint32_t co = (uint32_t)(ks * 256 + j * 32);
                uint32_t bH[2], bL[2];
                ldsm_x2(bH, hbase + RSM_HH + co);
                ldsm_x2(bL, hbase + RSM_HL + co);
                mma16816(acc, aH[j], bH);
                mma16816(acc, aH[j], bL);
                mma16816(acc, aL[j], bH);
            }
        }
        {
            float* part = (float*)(sm + RSM_PART);
            int r0 = ms * 16 + (lane >> 2);
            int bc = (lane & 3) * 2;
            part[(ks * 64 + r0) * 9 + bc]         = acc[0];
            part[(ks * 64 + r0) * 9 + bc + 1]     = acc[1];
            part[(ks * 64 + r0 + 8) * 9 + bc]     = acc[2];
            part[(ks * 64 + r0 + 8) * 9 + bc + 1] = acc[3];
        }
        __syncthreads();

        if (tid < 128) {
            const float* part = (const float*)(sm + RSM_PART);
            int m0 = en * 4;
            float s0 = part[m0 * 9 + eb] + part[(64 + m0) * 9 + eb]
                     + part[(128 + m0) * 9 + eb] + part[(192 + m0) * 9 + eb];
            float s1 = part[(m0 + 1) * 9 + eb] + part[(64 + m0 + 1) * 9 + eb]
                     + part[(128 + m0 + 1) * 9 + eb] + part[(192 + m0 + 1) * 9 + eb];
            float s2 = part[(m0 + 2) * 9 + eb] + part[(64 + m0 + 2) * 9 + eb]
                     + part[(128 + m0 + 2) * 9 + eb] + part[(192 + m0 + 2) * 9 + eb];
            float s3 = part[(m0 + 3) * 9 + eb] + part[(64 + m0 + 3) * 9 + eb]
                     + part[(128 + m0 + 3) * 9 + eb] + part[(192 + m0 + 3) * 9 + eb];

            float ig = 1.f / (1.f + __expf(-(s0 + xi)));
            float fg = 1.f / (1.f + __expf(-(s1 + xf)));
            float gg = 1.f / (1.f + __expf(-(s2 + xg)));
            float ct = 1.f - 2.f / (__expf(2.f * (s3 + xc)) + 1.f);

            float* cs = (float*)(sm + RSM_C);
            float c = fg * cs[tid] + ig * ct;
            cs[tid] = c;
            float h = gg * (1.f - 2.f / (__expf(2.f * c) + 1.f));

            int n = ci * 16 + en;
            int brow = bg * 8 + eb;
            __nv_bfloat16 hh = __float2bfloat16(h);
            __nv_bfloat16 hl = __float2bfloat16(h - __bfloat162float(hh));
            size_t ar = ((size_t)t * BSZ + brow) * (size_t)NSZ + n;
            g_Ahi[ar] = hh;
            g_Alo[ar] = hl;
            asm volatile("bar.sync 5, 128;");
            if (tid == 0) {
                __threadfence();
                int old = atomicAdd(cnt, 1);
                if (old == t * 8 + 7) st_rel(wfl, t + 1);
            }
        }
    }
}

// ---------------- launcher ---------------------------------------------------
extern "C" void kernel_launch(void* const* d_in, const int* in_sizes, int n_in,
                              void* d_out, int out_size)
{
    (void)in_sizes; (void)n_in; (void)out_size;
    const float* x   = (const float*)d_in[0];
    const float* W_i = (const float*)d_in[1];
    const float* U_i = (const float*)d_in[2];
    const float* W_f = (const float*)d_in[3];
    const float* U_f = (const float*)d_in[4];
    const float* W_g = (const float*)d_in[5];
    const float* U_g = (const float*)d_in[6];
    const float* W_c = (const float*)d_in[7];
    const float* U_c = (const float*)d_in[8];
    const float* W_o = (const float*)d_in[9];
    const float* b_i = (const float*)d_in[10];
    const float* b_f = (const float*)d_in[11];
    const float* b_g = (const float*)d_in[12];
    const float* b_c = (const float*)d_in[13];
    const float* b_o = (const float*)d_in[14];
    float* out = (float*)d_out;

    cudaFuncSetAttribute(lstm_recur_mma,
                         cudaFuncAttributeMaxDynamicSharedMemorySize, RSM_TOTAL);
    cudaFuncSetAttribute(gemm_mma_kernel,
                         cudaFuncAttributeMaxDynamicSharedMemorySize, GSM_TOTAL);

    cvt_x_kernel<<<(int)(((size_t)MROWS * DSZ / 4) / 256), 256>>>(x);
    prep_all_kernel<<<2054, 256>>>(W_i, W_f, W_g, W_c, U_i, U_f, U_g, U_c,
                                   b_i, b_f, b_g, b_c);
    gemm_mma_kernel<<<dim3(NCAT / 128, MROWS / 128), 256, GSM_TOTAL>>>(nullptr, nullptr, 0);
    lstm_recur_mma<<<128, 512, RSM_TOTAL>>>();
    {
        dim3 g(16, 16), b(32, 8);
        wtrans_kernel<<<g, b>>>(W_o, 0);
    }
    gemm_mma_kernel<<<dim3(NSZ / 128, MROWS / 128), 256, GSM_TOTAL>>>(b_o, out, 1);
}

// round 14
// speedup vs baseline: 1.1863x; 1.1863x over previous
#include <cuda_runtime.h>
#include <cuda_bf16.h>
#include <cstdint>
#include <cstddef>

#define BSZ 32
#define TSZ 2048
#define DSZ 512
#define NSZ 512
#define MROWS (BSZ * TSZ)      // 65536
#define NCAT  (4 * NSZ)        // 2048

// ---------------- device scratch (allocation-free: __device__ globals) -------
__device__ float  g_G[(size_t)TSZ * BSZ * NCAT];         // 512 MB  [t][b][gate*512+n]
__device__ __nv_bfloat16 g_Ahi[(size_t)MROWS * DSZ];     // 64 MB (x, then h history)
__device__ __nv_bfloat16 g_Alo[(size_t)MROWS * DSZ];     // 64 MB
__device__ __nv_bfloat16 g_Bhi[(size_t)NCAT * DSZ];      // 2 MB   [n][k] (W^T)
__device__ __nv_bfloat16 g_Blo[(size_t)NCAT * DSZ];      // 2 MB
__device__ __nv_bfloat16 g_UThi[(size_t)NCAT * DSZ];     // 2 MB   [n*4+gate][k]
__device__ __nv_bfloat16 g_UTlo[(size_t)NCAT * DSZ];     // 2 MB
__device__ __nv_bfloat16 g_h3H[3][BSZ * NSZ];            // depth-3 h (hi)
__device__ __nv_bfloat16 g_h3L[3][BSZ * NSZ];            // depth-3 h (lo)
__device__ float  g_biascat[NCAT];
__device__ int    g_pcnt[4 * 32];                        // per-batch-group counters

// ---------------- PTX helpers (baseline PTX: sm_80+ features only) ----------
__device__ __forceinline__ uint32_t smem_to_u32(const void* p) {
    uint32_t a;
    asm("{ .reg .u64 t; cvta.to.shared.u64 t, %1; cvt.u32.u64 %0, t; }" : "=r"(a) : "l"(p));
    return a;
}
#define CP_ASYNC16(dst, src) \
    asm volatile("cp.async.cg.shared.global [%0], [%1], 16;" :: "r"(dst), "l"(src))
#define CP_COMMIT() asm volatile("cp.async.commit_group;" ::: "memory")
#define CP_WAIT(n)  asm volatile("cp.async.wait_group %0;" :: "n"(n) : "memory")

__device__ __forceinline__ void ldsm_x4(uint32_t* r, uint32_t addr) {
    asm volatile("ldmatrix.sync.aligned.m8n8.x4.shared.b16 {%0,%1,%2,%3}, [%4];"
                 : "=r"(r[0]), "=r"(r[1]), "=r"(r[2]), "=r"(r[3]) : "r"(addr));
}
__device__ __forceinline__ void ldsm_x2(uint32_t* r, uint32_t addr) {
    asm volatile("ldmatrix.sync.aligned.m8n8.x2.shared.b16 {%0,%1}, [%2];"
                 : "=r"(r[0]), "=r"(r[1]) : "r"(addr));
}
__device__ __forceinline__ void mma16816(float* c, const uint32_t* a, const uint32_t* b) {
    asm volatile("mma.sync.aligned.m16n8k16.row.col.f32.bf16.bf16.f32 "
                 "{%0,%1,%2,%3}, {%4,%5,%6,%7}, {%8,%9}, {%0,%1,%2,%3};"
                 : "+f"(c[0]), "+f"(c[1]), "+f"(c[2]), "+f"(c[3])
                 : "r"(a[0]), "r"(a[1]), "r"(a[2]), "r"(a[3]), "r"(b[0]), "r"(b[1]));
}
__device__ __forceinline__ int ld_acq(const int* p) {
    int v;
    asm volatile("ld.acquire.gpu.global.b32 %0, [%1];" : "=r"(v) : "l"(p) : "memory");
    return v;
}

// ---------------- conversion helpers -----------------------------------------
__device__ __forceinline__ unsigned bf16pack2(float a, float b)
{
    return (unsigned)__bfloat16_as_ushort(__float2bfloat16(a)) |
           ((unsigned)__bfloat16_as_ushort(__float2bfloat16(b)) << 16);
}
__device__ __forceinline__ float bf16res(float a)
{
    return a - __bfloat162float(__float2bfloat16(a));
}

// ---------------- launch 0: x -> bf16 hi/lo ----------------------------------
__global__ void cvt_x_kernel(const float* __restrict__ src)
{
    size_t i = (size_t)blockIdx.x * 256 + threadIdx.x;
    float4 v = ((const float4*)src)[i];
    uint2 ph, pl;
    ph.x = bf16pack2(v.x, v.y);
    ph.y = bf16pack2(v.z, v.w);
    pl.x = bf16pack2(bf16res(v.x), bf16res(v.y));
    pl.y = bf16pack2(bf16res(v.z), bf16res(v.w));
    ((uint2*)g_Ahi)[i] = ph;
    ((uint2*)g_Alo)[i] = pl;
}

// ---------------- launch 1: mega-prep ----------------------------------------
__global__ void prep_all_kernel(
    const float* __restrict__ W0, const float* __restrict__ W1,
    const float* __restrict__ W2, const float* __restrict__ W3,
    const float* __restrict__ U0, const float* __restrict__ U1,
    const float* __restrict__ U2, const float* __restrict__ U3,
    const float* __restrict__ bi, const float* __restrict__ bf,
    const float* __restrict__ bg, const float* __restrict__ bc)
{
    __shared__ float t[32][33];
    const int bx  = blockIdx.x;
    const int tid = threadIdx.x;
    const int tx  = tid & 31;
    const int ty  = tid >> 5;

    if (bx < 1024) {                     // W transpose -> g_Bhi/g_Blo
        int z = bx >> 8, rem = bx & 255;
        const float* W = (z == 0) ? W0 : (z == 1) ? W1 : (z == 2) ? W2 : W3;
        int n0 = (rem & 15) * 32, k0 = (rem >> 4) * 32;
#pragma unroll
        for (int r = 0; r < 32; r += 8)
            t[ty + r][tx] = W[(size_t)(k0 + ty + r) * NSZ + n0 + tx];
        __syncthreads();
#pragma unroll
        for (int r = 0; r < 32; r += 8) {
            float v = t[tx][ty + r];
            size_t o = (size_t)(z * NSZ + n0 + ty + r) * DSZ + k0 + tx;
            g_Bhi[o] = __float2bfloat16(v);
            g_Blo[o] = __float2bfloat16(bf16res(v));
        }
    } else if (bx < 2048) {              // U transpose -> g_UThi/g_UTlo
        int idx = bx - 1024;
        int z = idx >> 8, rem = idx & 255;
        const float* U = (z == 0) ? U0 : (z == 1) ? U1 : (z == 2) ? U2 : U3;
        int n0 = (rem & 15) * 32, k0 = (rem >> 4) * 32;
#pragma unroll
        for (int r = 0; r < 32; r += 8)
            t[ty + r][tx] = U[(size_t)(k0 + ty + r) * NSZ + n0 + tx];
        __syncthreads();
#pragma unroll
        for (int r = 0; r < 32; r += 8) {
            float v = t[tx][ty + r];
            size_t o = ((size_t)(n0 + ty + r) * 4 + z) * DSZ + k0 + tx;
            g_UThi[o] = __float2bfloat16(v);
            g_UTlo[o] = __float2bfloat16(bf16res(v));
        }
    } else if (bx < 2050) {              // bias concat
        int i = (bx - 2048) * 256 + tid;
        g_biascat[i]           = bi[i];
        g_biascat[NSZ + i]     = bf[i];
        g_biascat[2 * NSZ + i] = bg[i];
        g_biascat[3 * NSZ + i] = bc[i];
    } else {                             // reset h buffers + counters
        int i = (bx - 2050) * 256 + tid;           // 0..8191
        for (int j = i; j < 12288; j += 8192) {
            if (j < 6144) ((uint4*)g_h3H)[j] = make_uint4(0, 0, 0, 0);
            else          ((uint4*)g_h3L)[j - 6144] = make_uint4(0, 0, 0, 0);
        }
        if (i < 128) g_pcnt[i] = 0;
    }
}

__global__ void wtrans_kernel(const float* __restrict__ W, int rowbase)
{
    __shared__ float t[32][33];
    int tx = threadIdx.x, ty = threadIdx.y;
    int n0 = blockIdx.x * 32, k0 = blockIdx.y * 32;
#pragma unroll
    for (int r = 0; r < 32; r += 8)
        t[ty + r][tx] = W[(size_t)(k0 + ty + r) * NSZ + n0 + tx];
    __syncthreads();
#pragma unroll
    for (int r = 0; r < 32; r += 8) {
        float v = t[tx][ty + r];
        size_t o = (size_t)(rowbase + n0 + ty + r) * DSZ + k0 + tx;
        g_Bhi[o] = __float2bfloat16(v);
        g_Blo[o] = __float2bfloat16(bf16res(v));
    }
}

// ---------------- HMMA GEMM (mma.sync bf16 hi/lo, fp32 accum) ----------------
#define GSM_TOTAL (2 * 65536)

__global__ __launch_bounds__(256, 1) void gemm_mma_kernel(
    const float* __restrict__ bias_ext, float* __restrict__ out_ext, int mode)
{
    extern __shared__ char smem[];
    const uint32_t smem_base = smem_to_u32(smem);
    const int tid  = threadIdx.x;
    const int wid  = tid >> 5;
    const int lane = tid & 31;
    const int wm   = wid & 1;
    const int wn   = wid >> 1;
    const int mbase = blockIdx.y * 128;
    const int nbase = blockIdx.x * 128;

    uint32_t dsts[16];
#pragma unroll
    for (int v = 0; v < 16; v++) {
        int row = (v & 3) * 32 + (tid >> 3);
        uint32_t off = row * 128 + (tid & 7) * 16;
        dsts[v] = (uint32_t)((v >> 2) * 16384) + (off ^ ((off >> 3) & 0x70));
    }

#define ISSUE_CHUNK(KT, BUFOFF) do {                                                 \
    int _kt = (KT);                                                                  \
    uint32_t _bo = (BUFOFF);                                                         \
    _Pragma("unroll")                                                                \
    for (int v = 0; v < 16; v++) {                                                   \
        const __nv_bfloat16* bp = (v < 4) ? g_Ahi : (v < 8) ? g_Alo                  \
                                  : (v < 12) ? g_Bhi : g_Blo;                        \
        int rb = (v < 8) ? mbase : nbase;                                            \
        int row = (v & 3) * 32 + (tid >> 3);                                         \
        CP_ASYNC16(smem_base + _bo + dsts[v],                                        \
                   bp + ((size_t)(rb + row) << 9) + _kt + ((tid & 7) << 3));         \
    }                                                                                \
    CP_COMMIT();                                                                     \
} while (0)

    uint32_t a_rowoff[4], a_swz[4];
#pragma unroll
    for (int mf = 0; mf < 4; mf++) {
        int row = wm * 64 + mf * 16 + (lane & 15);
        a_rowoff[mf] = row * 128;
        a_swz[mf]    = (row & 7) << 4;
    }
    const uint32_t a_cb = (uint32_t)(lane >> 4) * 16;
    uint32_t b_rowoff[4], b_swz[4];
#pragma unroll
    for (int nf = 0; nf < 4; nf++) {
        int row = wn * 32 + nf * 8 + (lane & 7);
        b_rowoff[nf] = row * 128;
        b_swz[nf]    = (row & 7) << 4;
    }
    const uint32_t b_cb = (uint32_t)((lane >> 3) & 1) * 16;

    float acc[4][4][4];
#pragma unroll
    for (int mf = 0; mf < 4; mf++)
#pragma unroll
        for (int nf = 0; nf < 4; nf++)
#pragma unroll
            for (int q = 0; q < 4; q++) acc[mf][nf][q] = 0.f;

    ISSUE_CHUNK(0, 0);

    for (int i = 0; i < 8; i++) {
        if (i < 7) {
            ISSUE_CHUNK((i + 1) * 64, (uint32_t)(((i + 1) & 1) * 65536));
            CP_WAIT(1);
        } else {
            CP_WAIT(0);
        }
        __syncthreads();

        const uint32_t base = smem_base + (uint32_t)((i & 1) * 65536);
#pragma unroll
        for (int k16 = 0; k16 < 4; k16++) {
            const uint32_t kb = (uint32_t)(k16 * 32);
            uint32_t aH[4][4], aL[4][4], bH[4][2], bL[4][2];
#pragma unroll
            for (int mf = 0; mf < 4; mf++) {
                uint32_t co = (kb + a_cb) ^ a_swz[mf];
                ldsm_x4(aH[mf], base + a_rowoff[mf] + co);
                ldsm_x4(aL[mf], base + 16384 + a_rowoff[mf] + co);
            }
#pragma unroll
            for (int nf = 0; nf < 4; nf++) {
                uint32_t co = (kb + b_cb) ^ b_swz[nf];
                ldsm_x2(bH[nf], base + 32768 + b_rowoff[nf] + co);
                ldsm_x2(bL[nf], base + 49152 + b_rowoff[nf] + co);
            }
#pragma unroll
            for (int mf = 0; mf < 4; mf++)
#pragma unroll
                for (int nf = 0; nf < 4; nf++) {
                    mma16816(acc[mf][nf], aH[mf], bH[nf]);
                    mma16816(acc[mf][nf], aH[mf], bL[nf]);
                    mma16816(acc[mf][nf], aL[mf], bH[nf]);
                }
        }
        __syncthreads();
    }

    const float* bias = mode ? bias_ext : g_biascat;
    float* C = mode ? out_ext : g_G;
    const int ncols = mode ? NSZ : NCAT;

#pragma unroll
    for (int mf = 0; mf < 4; mf++) {
#pragma unroll
        for (int h = 0; h < 2; h++) {
            int r = mbase + wm * 64 + mf * 16 + (lane >> 2) + h * 8;
            size_t crow;
            if (mode == 0) {
                int tt = r & (TSZ - 1), bb = r >> 11;
                crow = ((size_t)tt * BSZ + bb) * (size_t)ncols;
            } else {
                int tt = r >> 5, bb = r & 31;
                crow = ((size_t)bb * TSZ + tt) * (size_t)ncols;
            }
#pragma unroll
            for (int nf = 0; nf < 4; nf++) {
                int col = nbase + wn * 32 + nf * 8 + (lane & 3) * 2;
                float2 bv = *(const float2*)&bias[col];
                float2 o;
                o.x = acc[mf][nf][h * 2 + 0] + bv.x;
                o.y = acc[mf][nf][h * 2 + 1] + bv.y;
                if (mode) { o.x = fmaxf(o.x, 0.f); o.y = fmaxf(o.y, 0.f); }
                *(float2*)&C[crow + col] = o;
            }
        }
    }
#undef ISSUE_CHUNK
}

// ---------------- persistent MMA recurrence (batch-group partitioned) --------
// Identical structure to the 9089us kernel; only sync trims:
//  - consumers poll the group counter directly (no separate flag),
//  - release fence moved to tid0 after bar.sync 5 (CG pattern).
#define SH 1040
#define RSM_HH 0
#define RSM_HL (8 * SH)
#define RSM_PART (16 * SH)
#define RSM_C (RSM_PART + 9216)
#define RSM_TOTAL (128 * SH)

__global__ __launch_bounds__(512, 1) void lstm_recur_mma()
{
    extern __shared__ char sm[];
    const uint32_t sb = smem_to_u32(sm);
    const int tid  = threadIdx.x;
    const int wid  = tid >> 5;
    const int lane = tid & 31;
    const int ks   = wid & 3;
    const int ms   = wid >> 2;
    const int cta  = blockIdx.x;
    const int bg   = cta >> 5;
    const int ci   = cta & 31;

    // ---- one-time: stage UT slice (64 rows hi + 64 lo), build A-frags ----
#pragma unroll
    for (int q = 0; q < 16; q++) {
        int idx  = q * 512 + tid;
        int half = idx >> 12;
        int rem  = idx & 4095;
        int row  = rem >> 6, col = rem & 63;
        const __nv_bfloat16* src = half ? g_UTlo : g_UThi;
        CP_ASYNC16(sb + half * (64 * SH) + row * SH + col * 16,
                   src + ((size_t)(ci * 64 + row)) * DSZ + col * 8);
    }
    CP_COMMIT();
    CP_WAIT(0);
    __syncthreads();

    uint32_t aH[8][4], aL[8][4];
    {
        uint32_t rbase = sb + (ms * 16 + (lane & 15)) * SH + (lane >> 4) * 16;
#pragma unroll
        for (int j = 0; j < 8; j++) {
            uint32_t co = (uint32_t)(ks * 256 + j * 32);
            ldsm_x4(aH[j], rbase + co);
            ldsm_x4(aL[j], rbase + 64 * SH + co);
        }
    }
    __syncthreads();
    if (tid < 128) ((float*)(sm + RSM_C))[tid] = 0.f;
    __syncthreads();

    const int en = tid & 15;
    const int eb = tid >> 4;                   // valid for tid < 128

    float nxi = 0.f, nxf = 0.f, nxg = 0.f, nxc = 0.f;
    if (tid < 128) {
        size_t gb = (size_t)(bg * 8 + eb) * NCAT + (ci * 16 + en);
        nxi = __ldg(&g_G[gb]);
        nxf = __ldg(&g_G[gb + NSZ]);
        nxg = __ldg(&g_G[gb + 2 * NSZ]);
        nxc = __ldg(&g_G[gb + 3 * NSZ]);
    }

    const int lrow = lane >> 2;
    const uint32_t lcb = (uint32_t)(ks * 256 + (lane & 3) * 64);
    const uint32_t ldH = sb + RSM_HH + (uint32_t)lrow * SH + lcb;
    const uint32_t ldL = sb + RSM_HL + (uint32_t)lrow * SH + lcb;
    const uint32_t hbase = sb + (uint32_t)((lane & 7) * SH)
                         + (uint32_t)(((lane >> 3) & 1) * 16);

    int* cnt = &g_pcnt[bg * 32];

    int rbuf = 2, wbuf = 0;
    for (int t = 0; t < TSZ; t++) {
        const float xi = nxi, xf = nxf, xg = nxg, xc = nxc;

        if (wid < 4) {
            if (lane == 0) { while (ld_acq(cnt) < 32 * t) {} }
            __syncwarp();
            const char* sH = (const char*)(g_h3H[rbuf] + (bg * 8 + lrow) * NSZ) + lcb;
            const char* sL = (const char*)(g_h3L[rbuf] + (bg * 8 + lrow) * NSZ) + lcb;
#pragma unroll
            for (int i = 0; i < 4; i++) CP_ASYNC16(ldH + 16 * i, sH + 16 * i);
#pragma unroll
            for (int i = 0; i < 4; i++) CP_ASYNC16(ldL + 16 * i, sL + 16 * i);
            CP_COMMIT();
            if (t + 1 < TSZ) {                 // prefetch G(t+1), overlaps loads
                size_t gb = ((size_t)(t + 1) * BSZ + bg * 8 + eb) * (size_t)NCAT
                          + (ci * 16 + en);
                nxi = __ldg(&g_G[gb]);
                nxf = __ldg(&g_G[gb + NSZ]);
                nxg = __ldg(&g_G[gb + 2 * NSZ]);
                nxc = __ldg(&g_G[gb + 3 * NSZ]);
            }
            CP_WAIT(0);
        }
        asm volatile("bar.sync %0, 128;" :: "r"(1 + ks));

        float acc[4] = {0.f, 0.f, 0.f, 0.f};
#pragma unroll
        for (int j = 0; j < 8; j++) {
            uint32_t co = (uint32_t)(ks * 256 + j * 32);
            uint32_t bH[2], bL[2];
            ldsm_x2(bH, hbase + RSM_HH + co);
            ldsm_x2(bL, hbase + RSM_HL + co);
            mma16816(acc, aH[j], bH);
            mma16816(acc, aH[j], bL);
            mma16816(acc, aL[j], bH);
        }
        {
            float* part = (float*)(sm + RSM_PART);
            int r0 = ms * 16 + (lane >> 2);
            int bc = (lane & 3) * 2;
            part[(ks * 64 + r0) * 9 + bc]         = acc[0];
            part[(ks * 64 + r0) * 9 + bc + 1]     = acc[1];
            part[(ks * 64 + r0 + 8) * 9 + bc]     = acc[2];
            part[(ks * 64 + r0 + 8) * 9 + bc + 1] = acc[3];
        }
        __syncthreads();

        if (tid < 128) {
            const float* part = (const float*)(sm + RSM_PART);
            int m0 = en * 4;
            float s0 = part[m0 * 9 + eb] + part[(64 + m0) * 9 + eb]
                     + part[(128 + m0) * 9 + eb] + part[(192 + m0) * 9 + eb];
            float s1 = part[(m0 + 1) * 9 + eb] + part[(64 + m0 + 1) * 9 + eb]
                     + part[(128 + m0 + 1) * 9 + eb] + part[(192 + m0 + 1) * 9 + eb];
            float s2 = part[(m0 + 2) * 9 + eb] + part[(64 + m0 + 2) * 9 + eb]
                     + part[(128 + m0 + 2) * 9 + eb] + part[(192 + m0 + 2) * 9 + eb];
            float s3 = part[(m0 + 3) * 9 + eb] + part[(64 + m0 + 3) * 9 + eb]
                     + part[(128 + m0 + 3) * 9 + eb] + part[(192 + m0 + 3) * 9 + eb];

            float ig = 1.f / (1.f + __expf(-(s0 + xi)));
            float fg = 1.f / (1.f + __expf(-(s1 + xf)));
            float gg = 1.f / (1.f + __expf(-(s2 + xg)));
            float ct = 1.f - 2.f / (__expf(2.f * (s3 + xc)) + 1.f);

            float* cs = (float*)(sm + RSM_C);
            float c = fg * cs[tid] + ig * ct;
            cs[tid] = c;
            float h = gg * (1.f - 2.f / (__expf(2.f * c) + 1.f));

            int n = ci * 16 + en;
            int brow = bg * 8 + eb;
            __nv_bfloat16 hh = __float2bfloat16(h);
            __nv_bfloat16 hl = __float2bfloat16(h - __bfloat162float(hh));
            g_h3H[wbuf][brow * NSZ + n] = hh;
            g_h3L[wbuf][brow * NSZ + n] = hl;
            size_t ar = ((size_t)t * BSZ + brow) * (size_t)NSZ + n;
            g_Ahi[ar] = hh;
            g_Alo[ar] = hl;
            asm volatile("bar.sync 5, 128;");
            if (tid == 0) {
                __threadfence();
                atomicAdd(cnt, 1);             // return unused -> REDG
            }
        }

        rbuf = (rbuf == 2) ? 0 : rbuf + 1;
        wbuf = (wbuf == 2) ? 0 : wbuf + 1;
    }
}

// ---------------- launcher ---------------------------------------------------
extern "C" void kernel_launch(void* const* d_in, const int* in_sizes, int n_in,
                              void* d_out, int out_size)
{
    (void)in_sizes; (void)n_in; (void)out_size;
    const float* x   = (const float*)d_in[0];
    const float* W_i = (const float*)d_in[1];
    const float* U_i = (const float*)d_in[2];
    const float* W_f = (const float*)d_in[3];
    const float* U_f = (const float*)d_in[4];
    const float* W_g = (const float*)d_in[5];
    const float* U_g = (const float*)d_in[6];
    const float* W_c = (const float*)d_in[7];
    const float* U_c = (const float*)d_in[8];
    const float* W_o = (const float*)d_in[9];
    const float* b_i = (const float*)d_in[10];
    const float* b_f = (const float*)d_in[11];
    const float* b_g = (const float*)d_in[12];
    const float* b_c = (const float*)d_in[13];
    const float* b_o = (const float*)d_in[14];
    float* out = (float*)d_out;

    cudaFuncSetAttribute(lstm_recur_mma,
                         cudaFuncAttributeMaxDynamicSharedMemorySize, RSM_TOTAL);
    cudaFuncSetAttribute(gemm_mma_kernel,
                         cudaFuncAttributeMaxDynamicSharedMemorySize, GSM_TOTAL);

    cvt_x_kernel<<<(int)(((size_t)MROWS * DSZ / 4) / 256), 256>>>(x);
    prep_all_kernel<<<2082, 256>>>(W_i, W_f, W_g, W_c, U_i, U_f, U_g, U_c,
                                   b_i, b_f, b_g, b_c);
    gemm_mma_kernel<<<dim3(NCAT / 128, MROWS / 128), 256, GSM_TOTAL>>>(nullptr, nullptr, 0);
    lstm_recur_mma<<<128, 512, RSM_TOTAL>>>();
    {
        dim3 g(16, 16), b(32, 8);
        wtrans_kernel<<<g, b>>>(W_o, 0);
    }
    gemm_mma_kernel<<<dim3(NSZ / 128, MROWS / 128), 256, GSM_TOTAL>>>(b_o, out, 1);
}

// round 15
// speedup vs baseline: 1.1897x; 1.0028x over previous
#include <cuda_runtime.h>
#include <cuda_bf16.h>
#include <cstdint>
#include <cstddef>

#define BSZ 32
#define TSZ 2048
#define DSZ 512
#define NSZ 512
#define MROWS (BSZ * TSZ)      // 65536
#define NCAT  (4 * NSZ)        // 2048

// ---------------- device scratch (allocation-free: __device__ globals) -------
__device__ float  g_G[(size_t)TSZ * BSZ * NCAT];         // 512 MB  [t][b][gate*512+n]
__device__ __nv_bfloat16 g_Ahi[(size_t)MROWS * DSZ];     // 64 MB (x, then h history)
__device__ __nv_bfloat16 g_Alo[(size_t)MROWS * DSZ];     // 64 MB
__device__ __nv_bfloat16 g_Bhi[(size_t)NCAT * DSZ];      // 2 MB   [n][k] (W^T)
__device__ __nv_bfloat16 g_Blo[(size_t)NCAT * DSZ];      // 2 MB
__device__ __nv_bfloat16 g_UThi[(size_t)NCAT * DSZ];     // 2 MB   [n*4+gate][k]
__device__ __nv_bfloat16 g_UTlo[(size_t)NCAT * DSZ];     // 2 MB
__device__ __nv_bfloat16 g_h3H[3][BSZ * NSZ];            // depth-3 h (hi)
__device__ __nv_bfloat16 g_h3L[3][BSZ * NSZ];            // depth-3 h (lo)
__device__ float  g_biascat[NCAT];
__device__ int    g_pcnt[4 * 32];                        // per-batch-group counters

// ---------------- PTX helpers (baseline PTX: sm_80+ features only) ----------
__device__ __forceinline__ uint32_t smem_to_u32(const void* p) {
    uint32_t a;
    asm("{ .reg .u64 t; cvta.to.shared.u64 t, %1; cvt.u32.u64 %0, t; }" : "=r"(a) : "l"(p));
    return a;
}
#define CP_ASYNC16(dst, src) \
    asm volatile("cp.async.cg.shared.global [%0], [%1], 16;" :: "r"(dst), "l"(src))
#define CP_COMMIT() asm volatile("cp.async.commit_group;" ::: "memory")
#define CP_WAIT(n)  asm volatile("cp.async.wait_group %0;" :: "n"(n) : "memory")

__device__ __forceinline__ void ldsm_x4(uint32_t* r, uint32_t addr) {
    asm volatile("ldmatrix.sync.aligned.m8n8.x4.shared.b16 {%0,%1,%2,%3}, [%4];"
                 : "=r"(r[0]), "=r"(r[1]), "=r"(r[2]), "=r"(r[3]) : "r"(addr));
}
__device__ __forceinline__ void ldsm_x2(uint32_t* r, uint32_t addr) {
    asm volatile("ldmatrix.sync.aligned.m8n8.x2.shared.b16 {%0,%1}, [%2];"
                 : "=r"(r[0]), "=r"(r[1]) : "r"(addr));
}
__device__ __forceinline__ void mma16816(float* c, const uint32_t* a, const uint32_t* b) {
    asm volatile("mma.sync.aligned.m16n8k16.row.col.f32.bf16.bf16.f32 "
                 "{%0,%1,%2,%3}, {%4,%5,%6,%7}, {%8,%9}, {%0,%1,%2,%3};"
                 : "+f"(c[0]), "+f"(c[1]), "+f"(c[2]), "+f"(c[3])
                 : "r"(a[0]), "r"(a[1]), "r"(a[2]), "r"(a[3]), "r"(b[0]), "r"(b[1]));
}
__device__ __forceinline__ int ld_acq(const int* p) {
    int v;
    asm volatile("ld.acquire.gpu.global.b32 %0, [%1];" : "=r"(v) : "l"(p) : "memory");
    return v;
}

// ---------------- conversion helpers -----------------------------------------
__device__ __forceinline__ unsigned bf16pack2(float a, float b)
{
    return (unsigned)__bfloat16_as_ushort(__float2bfloat16(a)) |
           ((unsigned)__bfloat16_as_ushort(__float2bfloat16(b)) << 16);
}
__device__ __forceinline__ float bf16res(float a)
{
    return a - __bfloat162float(__float2bfloat16(a));
}

// ---------------- launch 0: x -> bf16 hi/lo ----------------------------------
__global__ void cvt_x_kernel(const float* __restrict__ src)
{
    size_t i = (size_t)blockIdx.x * 256 + threadIdx.x;
    float4 v = ((const float4*)src)[i];
    uint2 ph, pl;
    ph.x = bf16pack2(v.x, v.y);
    ph.y = bf16pack2(v.z, v.w);
    pl.x = bf16pack2(bf16res(v.x), bf16res(v.y));
    pl.y = bf16pack2(bf16res(v.z), bf16res(v.w));
    ((uint2*)g_Ahi)[i] = ph;
    ((uint2*)g_Alo)[i] = pl;
}

// ---------------- launch 1: mega-prep ----------------------------------------
__global__ void prep_all_kernel(
    const float* __restrict__ W0, const float* __restrict__ W1,
    const float* __restrict__ W2, const float* __restrict__ W3,
    const float* __restrict__ U0, const float* __restrict__ U1,
    const float* __restrict__ U2, const float* __restrict__ U3,
    const float* __restrict__ bi, const float* __restrict__ bf,
    const float* __restrict__ bg, const float* __restrict__ bc)
{
    __shared__ float t[32][33];
    const int bx  = blockIdx.x;
    const int tid = threadIdx.x;
    const int tx  = tid & 31;
    const int ty  = tid >> 5;

    if (bx < 1024) {                     // W transpose -> g_Bhi/g_Blo
        int z = bx >> 8, rem = bx & 255;
        const float* W = (z == 0) ? W0 : (z == 1) ? W1 : (z == 2) ? W2 : W3;
        int n0 = (rem & 15) * 32, k0 = (rem >> 4) * 32;
#pragma unroll
        for (int r = 0; r < 32; r += 8)
            t[ty + r][tx] = W[(size_t)(k0 + ty + r) * NSZ + n0 + tx];
        __syncthreads();
#pragma unroll
        for (int r = 0; r < 32; r += 8) {
            float v = t[tx][ty + r];
            size_t o = (size_t)(z * NSZ + n0 + ty + r) * DSZ + k0 + tx;
            g_Bhi[o] = __float2bfloat16(v);
            g_Blo[o] = __float2bfloat16(bf16res(v));
        }
    } else if (bx < 2048) {              // U transpose -> g_UThi/g_UTlo
        int idx = bx - 1024;
        int z = idx >> 8, rem = idx & 255;
        const float* U = (z == 0) ? U0 : (z == 1) ? U1 : (z == 2) ? U2 : U3;
        int n0 = (rem & 15) * 32, k0 = (rem >> 4) * 32;
#pragma unroll
        for (int r = 0; r < 32; r += 8)
            t[ty + r][tx] = U[(size_t)(k0 + ty + r) * NSZ + n0 + tx];
        __syncthreads();
#pragma unroll
        for (int r = 0; r < 32; r += 8) {
            float v = t[tx][ty + r];
            size_t o = ((size_t)(n0 + ty + r) * 4 + z) * DSZ + k0 + tx;
            g_UThi[o] = __float2bfloat16(v);
            g_UTlo[o] = __float2bfloat16(bf16res(v));
        }
    } else if (bx < 2050) {              // bias concat
        int i = (bx - 2048) * 256 + tid;
        g_biascat[i]           = bi[i];
        g_biascat[NSZ + i]     = bf[i];
        g_biascat[2 * NSZ + i] = bg[i];
        g_biascat[3 * NSZ + i] = bc[i];
    } else {                             // reset h buffers + counters
        int i = (bx - 2050) * 256 + tid;           // 0..8191
        for (int j = i; j < 12288; j += 8192) {
            if (j < 6144) ((uint4*)g_h3H)[j] = make_uint4(0, 0, 0, 0);
            else          ((uint4*)g_h3L)[j - 6144] = make_uint4(0, 0, 0, 0);
        }
        if (i < 128) g_pcnt[i] = 0;
    }
}

__global__ void wtrans_kernel(const float* __restrict__ W, int rowbase)
{
    __shared__ float t[32][33];
    int tx = threadIdx.x, ty = threadIdx.y;
    int n0 = blockIdx.x * 32, k0 = blockIdx.y * 32;
#pragma unroll
    for (int r = 0; r < 32; r += 8)
        t[ty + r][tx] = W[(size_t)(k0 + ty + r) * NSZ + n0 + tx];
    __syncthreads();
#pragma unroll
    for (int r = 0; r < 32; r += 8) {
        float v = t[tx][ty + r];
        size_t o = (size_t)(rowbase + n0 + ty + r) * DSZ + k0 + tx;
        g_Bhi[o] = __float2bfloat16(v);
        g_Blo[o] = __float2bfloat16(bf16res(v));
    }
}

// ---------------- HMMA GEMM (mma.sync bf16 hi/lo, fp32 accum) ----------------
#define GSM_TOTAL (2 * 65536)

__global__ __launch_bounds__(256, 1) void gemm_mma_kernel(
    const float* __restrict__ bias_ext, float* __restrict__ out_ext, int mode)
{
    extern __shared__ char smem[];
    const uint32_t smem_base = smem_to_u32(smem);
    const int tid  = threadIdx.x;
    const int wid  = tid >> 5;
    const int lane = tid & 31;
    const int wm   = wid & 1;
    const int wn   = wid >> 1;
    const int mbase = blockIdx.y * 128;
    const int nbase = blockIdx.x * 128;

    uint32_t dsts[16];
#pragma unroll
    for (int v = 0; v < 16; v++) {
        int row = (v & 3) * 32 + (tid >> 3);
        uint32_t off = row * 128 + (tid & 7) * 16;
        dsts[v] = (uint32_t)((v >> 2) * 16384) + (off ^ ((off >> 3) & 0x70));
    }

#define ISSUE_CHUNK(KT, BUFOFF) do {                                                 \
    int _kt = (KT);                                                                  \
    uint32_t _bo = (BUFOFF);                                                         \
    _Pragma("unroll")                                                                \
    for (int v = 0; v < 16; v++) {                                                   \
        const __nv_bfloat16* bp = (v < 4) ? g_Ahi : (v < 8) ? g_Alo                  \
                                  : (v < 12) ? g_Bhi : g_Blo;                        \
        int rb = (v < 8) ? mbase : nbase;                                            \
        int row = (v & 3) * 32 + (tid >> 3);                                         \
        CP_ASYNC16(smem_base + _bo + dsts[v],                                        \
                   bp + ((size_t)(rb + row) << 9) + _kt + ((tid & 7) << 3));         \
    }                                                                                \
    CP_COMMIT();                                                                     \
} while (0)

    uint32_t a_rowoff[4], a_swz[4];
#pragma unroll
    for (int mf = 0; mf < 4; mf++) {
        int row = wm * 64 + mf * 16 + (lane & 15);
        a_rowoff[mf] = row * 128;
        a_swz[mf]    = (row & 7) << 4;
    }
    const uint32_t a_cb = (uint32_t)(lane >> 4) * 16;
    uint32_t b_rowoff[4], b_swz[4];
#pragma unroll
    for (int nf = 0; nf < 4; nf++) {
        int row = wn * 32 + nf * 8 + (lane & 7);
        b_rowoff[nf] = row * 128;
        b_swz[nf]    = (row & 7) << 4;
    }
    const uint32_t b_cb = (uint32_t)((lane >> 3) & 1) * 16;

    float acc[4][4][4];
#pragma unroll
    for (int mf = 0; mf < 4; mf++)
#pragma unroll
        for (int nf = 0; nf < 4; nf++)
#pragma unroll
            for (int q = 0; q < 4; q++) acc[mf][nf][q] = 0.f;

    ISSUE_CHUNK(0, 0);

    for (int i = 0; i < 8; i++) {
        if (i < 7) {
            ISSUE_CHUNK((i + 1) * 64, (uint32_t)(((i + 1) & 1) * 65536));
            CP_WAIT(1);
        } else {
            CP_WAIT(0);
        }
        __syncthreads();

        const uint32_t base = smem_base + (uint32_t)((i & 1) * 65536);
#pragma unroll
        for (int k16 = 0; k16 < 4; k16++) {
            const uint32_t kb = (uint32_t)(k16 * 32);
            uint32_t aH[4][4], aL[4][4], bH[4][2], bL[4][2];
#pragma unroll
            for (int mf = 0; mf < 4; mf++) {
                uint32_t co = (kb + a_cb) ^ a_swz[mf];
                ldsm_x4(aH[mf], base + a_rowoff[mf] + co);
                ldsm_x4(aL[mf], base + 16384 + a_rowoff[mf] + co);
            }
#pragma unroll
            for (int nf = 0; nf < 4; nf++) {
                uint32_t co = (kb + b_cb) ^ b_swz[nf];
                ldsm_x2(bH[nf], base + 32768 + b_rowoff[nf] + co);
                ldsm_x2(bL[nf], base + 49152 + b_rowoff[nf] + co);
            }
#pragma unroll
            for (int mf = 0; mf < 4; mf++)
#pragma unroll
                for (int nf = 0; nf < 4; nf++) {
                    mma16816(acc[mf][nf], aH[mf], bH[nf]);
                    mma16816(acc[mf][nf], aH[mf], bL[nf]);
                    mma16816(acc[mf][nf], aL[mf], bH[nf]);
                }
        }
        __syncthreads();
    }

    const float* bias = mode ? bias_ext : g_biascat;
    float* C = mode ? out_ext : g_G;
    const int ncols = mode ? NSZ : NCAT;

#pragma unroll
    for (int mf = 0; mf < 4; mf++) {
#pragma unroll
        for (int h = 0; h < 2; h++) {
            int r = mbase + wm * 64 + mf * 16 + (lane >> 2) + h * 8;
            size_t crow;
            if (mode == 0) {
                int tt = r & (TSZ - 1), bb = r >> 11;
                crow = ((size_t)tt * BSZ + bb) * (size_t)ncols;
            } else {
                int tt = r >> 5, bb = r & 31;
                crow = ((size_t)bb * TSZ + tt) * (size_t)ncols;
            }
#pragma unroll
            for (int nf = 0; nf < 4; nf++) {
                int col = nbase + wn * 32 + nf * 8 + (lane & 3) * 2;
                float2 bv = *(const float2*)&bias[col];
                float2 o;
                o.x = acc[mf][nf][h * 2 + 0] + bv.x;
                o.y = acc[mf][nf][h * 2 + 1] + bv.y;
                if (mode) { o.x = fmaxf(o.x, 0.f); o.y = fmaxf(o.y, 0.f); }
                *(float2*)&C[crow + col] = o;
            }
        }
    }
#undef ISSUE_CHUNK
}

// ---------------- persistent MMA recurrence (batch-group partitioned) --------
// R14 structure; R15 deltas: 3 split accumulators (shorter HMMA RAW chain),
// h-history stores moved after the release (not fence-covered; consumed only
// by the next kernel launch).
#define SH 1040
#define RSM_HH 0
#define RSM_HL (8 * SH)
#define RSM_PART (16 * SH)
#define RSM_C (RSM_PART + 9216)
#define RSM_TOTAL (128 * SH)

__global__ __launch_bounds__(512, 1) void lstm_recur_mma()
{
    extern __shared__ char sm[];
    const uint32_t sb = smem_to_u32(sm);
    const int tid  = threadIdx.x;
    const int wid  = tid >> 5;
    const int lane = tid & 31;
    const int ks   = wid & 3;
    const int ms   = wid >> 2;
    const int cta  = blockIdx.x;
    const int bg   = cta >> 5;
    const int ci   = cta & 31;

    // ---- one-time: stage UT slice (64 rows hi + 64 lo), build A-frags ----
#pragma unroll
    for (int q = 0; q < 16; q++) {
        int idx  = q * 512 + tid;
        int half = idx >> 12;
        int rem  = idx & 4095;
        int row  = rem >> 6, col = rem & 63;
        const __nv_bfloat16* src = half ? g_UTlo : g_UThi;
        CP_ASYNC16(sb + half * (64 * SH) + row * SH + col * 16,
                   src + ((size_t)(ci * 64 + row)) * DSZ + col * 8);
    }
    CP_COMMIT();
    CP_WAIT(0);
    __syncthreads();

    uint32_t aH[8][4], aL[8][4];
    {
        uint32_t rbase = sb + (ms * 16 + (lane & 15)) * SH + (lane >> 4) * 16;
#pragma unroll
        for (int j = 0; j < 8; j++) {
            uint32_t co = (uint32_t)(ks * 256 + j * 32);
            ldsm_x4(aH[j], rbase + co);
            ldsm_x4(aL[j], rbase + 64 * SH + co);
        }
    }
    __syncthreads();
    if (tid < 128) ((float*)(sm + RSM_C))[tid] = 0.f;
    __syncthreads();

    const int en = tid & 15;
    const int eb = tid >> 4;                   // valid for tid < 128

    float nxi = 0.f, nxf = 0.f, nxg = 0.f, nxc = 0.f;
    if (tid < 128) {
        size_t gb = (size_t)(bg * 8 + eb) * NCAT + (ci * 16 + en);
        nxi = __ldg(&g_G[gb]);
        nxf = __ldg(&g_G[gb + NSZ]);
        nxg = __ldg(&g_G[gb + 2 * NSZ]);
        nxc = __ldg(&g_G[gb + 3 * NSZ]);
    }

    const int lrow = lane >> 2;
    const uint32_t lcb = (uint32_t)(ks * 256 + (lane & 3) * 64);
    const uint32_t ldH = sb + RSM_HH + (uint32_t)lrow * SH + lcb;
    const uint32_t ldL = sb + RSM_HL + (uint32_t)lrow * SH + lcb;
    const uint32_t hbase = sb + (uint32_t)((lane & 7) * SH)
                         + (uint32_t)(((lane >> 3) & 1) * 16);

    int* cnt = &g_pcnt[bg * 32];

    int rbuf = 2, wbuf = 0;
    for (int t = 0; t < TSZ; t++) {
        const float xi = nxi, xf = nxf, xg = nxg, xc = nxc;

        if (wid < 4) {
            if (lane == 0) { while (ld_acq(cnt) < 32 * t) {} }
            __syncwarp();
            const char* sH = (const char*)(g_h3H[rbuf] + (bg * 8 + lrow) * NSZ) + lcb;
            const char* sL = (const char*)(g_h3L[rbuf] + (bg * 8 + lrow) * NSZ) + lcb;
#pragma unroll
            for (int i = 0; i < 4; i++) CP_ASYNC16(ldH + 16 * i, sH + 16 * i);
#pragma unroll
            for (int i = 0; i < 4; i++) CP_ASYNC16(ldL + 16 * i, sL + 16 * i);
            CP_COMMIT();
            if (t + 1 < TSZ) {                 // prefetch G(t+1), overlaps loads
                size_t gb = ((size_t)(t + 1) * BSZ + bg * 8 + eb) * (size_t)NCAT
                          + (ci * 16 + en);
                nxi = __ldg(&g_G[gb]);
                nxf = __ldg(&g_G[gb + NSZ]);
                nxg = __ldg(&g_G[gb + 2 * NSZ]);
                nxc = __ldg(&g_G[gb + 3 * NSZ]);
            }
            CP_WAIT(0);
        }
        asm volatile("bar.sync %0, 128;" :: "r"(1 + ks));

        // 3 split accumulators -> RAW chains of 8 instead of 24
        float a0[4] = {0.f, 0.f, 0.f, 0.f};
        float a1[4] = {0.f, 0.f, 0.f, 0.f};
        float a2[4] = {0.f, 0.f, 0.f, 0.f};
#pragma unroll
        for (int j = 0; j < 8; j++) {
            uint32_t co = (uint32_t)(ks * 256 + j * 32);
            uint32_t bH[2], bL[2];
            ldsm_x2(bH, hbase + RSM_HH + co);
            ldsm_x2(bL, hbase + RSM_HL + co);
            mma16816(a0, aH[j], bH);
            mma16816(a1, aH[j], bL);
            mma16816(a2, aL[j], bH);
        }
        {
            float* part = (float*)(sm + RSM_PART);
            int r0 = ms * 16 + (lane >> 2);
            int bc = (lane & 3) * 2;
            part[(ks * 64 + r0) * 9 + bc]         = a0[0] + a1[0] + a2[0];
            part[(ks * 64 + r0) * 9 + bc + 1]     = a0[1] + a1[1] + a2[1];
            part[(ks * 64 + r0 + 8) * 9 + bc]     = a0[2] + a1[2] + a2[2];
            part[(ks * 64 + r0 + 8) * 9 + bc + 1] = a0[3] + a1[3] + a2[3];
        }
        __syncthreads();

        if (tid < 128) {
            const float* part = (const float*)(sm + RSM_PART);
            int m0 = en * 4;
            float s0 = part[m0 * 9 + eb] + part[(64 + m0) * 9 + eb]
                     + part[(128 + m0) * 9 + eb] + part[(192 + m0) * 9 + eb];
            float s1 = part[(m0 + 1) * 9 + eb] + part[(64 + m0 + 1) * 9 + eb]
                     + part[(128 + m0 + 1) * 9 + eb] + part[(192 + m0 + 1) * 9 + eb];
            float s2 = part[(m0 + 2) * 9 + eb] + part[(64 + m0 + 2) * 9 + eb]
                     + part[(128 + m0 + 2) * 9 + eb] + part[(192 + m0 + 2) * 9 + eb];
            float s3 = part[(m0 + 3) * 9 + eb] + part[(64 + m0 + 3) * 9 + eb]
                     + part[(128 + m0 + 3) * 9 + eb] + part[(192 + m0 + 3) * 9 + eb];

            float ig = 1.f / (1.f + __expf(-(s0 + xi)));
            float fg = 1.f / (1.f + __expf(-(s1 + xf)));
            float gg = 1.f / (1.f + __expf(-(s2 + xg)));
            float ct = 1.f - 2.f / (__expf(2.f * (s3 + xc)) + 1.f);

            float* cs = (float*)(sm + RSM_C);
            float c = fg * cs[tid] + ig * ct;
            cs[tid] = c;
            float h = gg * (1.f - 2.f / (__expf(2.f * c) + 1.f));

            int n = ci * 16 + en;
            int brow = bg * 8 + eb;
            __nv_bfloat16 hh = __float2bfloat16(h);
            __nv_bfloat16 hl = __float2bfloat16(h - __bfloat162float(hh));
            // exchange stores first (fence-covered), release, then history
            g_h3H[wbuf][brow * NSZ + n] = hh;
            g_h3L[wbuf][brow * NSZ + n] = hl;
            asm volatile("bar.sync 5, 128;");
            if (tid == 0) {
                __threadfence();
                atomicAdd(cnt, 1);             // return unused -> REDG
            }
            size_t ar = ((size_t)t * BSZ + brow) * (size_t)NSZ + n;
            g_Ahi[ar] = hh;                    // consumed only after kernel exit
            g_Alo[ar] = hl;
        }

        rbuf = (rbuf == 2) ? 0 : rbuf + 1;
        wbuf = (wbuf == 2) ? 0 : wbuf + 1;
    }
}

// ---------------- launcher ---------------------------------------------------
extern "C" void kernel_launch(void* const* d_in, const int* in_sizes, int n_in,
                              void* d_out, int out_size)
{
    (void)in_sizes; (void)n_in; (void)out_size;
    const float* x   = (const float*)d_in[0];
    const float* W_i = (const float*)d_in[1];
    const float* U_i = (const float*)d_in[2];
    const float* W_f = (const float*)d_in[3];
    const float* U_f = (const float*)d_in[4];
    const float* W_g = (const float*)d_in[5];
    const float* U_g = (const float*)d_in[6];
    const float* W_c = (const float*)d_in[7];
    const float* U_c = (const float*)d_in[8];
    const float* W_o = (const float*)d_in[9];
    const float* b_i = (const float*)d_in[10];
    const float* b_f = (const float*)d_in[11];
    const float* b_g = (const float*)d_in[12];
    const float* b_c = (const float*)d_in[13];
    const float* b_o = (const float*)d_in[14];
    float* out = (float*)d_out;

    cudaFuncSetAttribute(lstm_recur_mma,
                         cudaFuncAttributeMaxDynamicSharedMemorySize, RSM_TOTAL);
    cudaFuncSetAttribute(gemm_mma_kernel,
                         cudaFuncAttributeMaxDynamicSharedMemorySize, GSM_TOTAL);

    cvt_x_kernel<<<(int)(((size_t)MROWS * DSZ / 4) / 256), 256>>>(x);
    prep_all_kernel<<<2082, 256>>>(W_i, W_f, W_g, W_c, U_i, U_f, U_g, U_c,
                                   b_i, b_f, b_g, b_c);
    gemm_mma_kernel<<<dim3(NCAT / 128, MROWS / 128), 256, GSM_TOTAL>>>(nullptr, nullptr, 0);
    lstm_recur_mma<<<128, 512, RSM_TOTAL>>>();
    {
        dim3 g(16, 16), b(32, 8);
        wtrans_kernel<<<g, b>>>(W_o, 0);
    }
    gemm_mma_kernel<<<dim3(NSZ / 128, MROWS / 128), 256, GSM_TOTAL>>>(b_o, out, 1);
}

// round 16
// speedup vs baseline: 1.2664x; 1.0645x over previous
#include <cuda_runtime.h>
#include <cuda_bf16.h>
#include <cstdint>
#include <cstddef>

#define BSZ 32
#define TSZ 2048
#define DSZ 512
#define NSZ 512
#define MROWS (BSZ * TSZ)      // 65536
#define NCAT  (4 * NSZ)        // 2048

// ---------------- device scratch (allocation-free: __device__ globals) -------
__device__ float  g_G[(size_t)TSZ * BSZ * NCAT];         // 512 MB  [t][b][gate*512+n]
__device__ __nv_bfloat16 g_Ahi[(size_t)MROWS * DSZ];     // 64 MB (x, then h history)
__device__ __nv_bfloat16 g_Alo[(size_t)MROWS * DSZ];     // 64 MB
__device__ __nv_bfloat16 g_Bhi[(size_t)NCAT * DSZ];      // 2 MB   [n][k] (W^T)
__device__ __nv_bfloat16 g_Blo[(size_t)NCAT * DSZ];      // 2 MB
__device__ __nv_bfloat16 g_UThi[(size_t)NCAT * DSZ];     // 2 MB   [n*4+gate][k]
__device__ __nv_bfloat16 g_UTlo[(size_t)NCAT * DSZ];     // 2 MB
__device__ __nv_bfloat16 g_h3H[3][BSZ * NSZ];            // depth-3 h (hi)
__device__ __nv_bfloat16 g_h3L[3][BSZ * NSZ];            // depth-3 h (lo)
__device__ float  g_biascat[NCAT];
__device__ int    g_pcnt[4 * 8 * 32];                    // (bg, sub) counters, 128B apart

// ---------------- PTX helpers (baseline PTX: sm_80+ features only) ----------
__device__ __forceinline__ uint32_t smem_to_u32(const void* p) {
    uint32_t a;
    asm("{ .reg .u64 t; cvta.to.shared.u64 t, %1; cvt.u32.u64 %0, t; }" : "=r"(a) : "l"(p));
    return a;
}
#define CP_ASYNC16(dst, src) \
    asm volatile("cp.async.cg.shared.global [%0], [%1], 16;" :: "r"(dst), "l"(src))
#define CP_COMMIT() asm volatile("cp.async.commit_group;" ::: "memory")
#define CP_WAIT(n)  asm volatile("cp.async.wait_group %0;" :: "n"(n) : "memory")

__device__ __forceinline__ void ldsm_x4(uint32_t* r, uint32_t addr) {
    asm volatile("ldmatrix.sync.aligned.m8n8.x4.shared.b16 {%0,%1,%2,%3}, [%4];"
                 : "=r"(r[0]), "=r"(r[1]), "=r"(r[2]), "=r"(r[3]) : "r"(addr));
}
__device__ __forceinline__ void ldsm_x2(uint32_t* r, uint32_t addr) {
    asm volatile("ldmatrix.sync.aligned.m8n8.x2.shared.b16 {%0,%1}, [%2];"
                 : "=r"(r[0]), "=r"(r[1]) : "r"(addr));
}
__device__ __forceinline__ void mma16816(float* c, const uint32_t* a, const uint32_t* b) {
    asm volatile("mma.sync.aligned.m16n8k16.row.col.f32.bf16.bf16.f32 "
                 "{%0,%1,%2,%3}, {%4,%5,%6,%7}, {%8,%9}, {%0,%1,%2,%3};"
                 : "+f"(c[0]), "+f"(c[1]), "+f"(c[2]), "+f"(c[3])
                 : "r"(a[0]), "r"(a[1]), "r"(a[2]), "r"(a[3]), "r"(b[0]), "r"(b[1]));
}
__device__ __forceinline__ int ld_acq(const int* p) {
    int v;
    asm volatile("ld.acquire.gpu.global.b32 %0, [%1];" : "=r"(v) : "l"(p) : "memory");
    return v;
}

// ---------------- conversion helpers -----------------------------------------
__device__ __forceinline__ unsigned bf16pack2(float a, float b)
{
    return (unsigned)__bfloat16_as_ushort(__float2bfloat16(a)) |
           ((unsigned)__bfloat16_as_ushort(__float2bfloat16(b)) << 16);
}
__device__ __forceinline__ float bf16res(float a)
{
    return a - __bfloat162float(__float2bfloat16(a));
}

// ---------------- launch 0: x -> bf16 hi/lo ----------------------------------
__global__ void cvt_x_kernel(const float* __restrict__ src)
{
    size_t i = (size_t)blockIdx.x * 256 + threadIdx.x;
    float4 v = ((const float4*)src)[i];
    uint2 ph, pl;
    ph.x = bf16pack2(v.x, v.y);
    ph.y = bf16pack2(v.z, v.w);
    pl.x = bf16pack2(bf16res(v.x), bf16res(v.y));
    pl.y = bf16pack2(bf16res(v.z), bf16res(v.w));
    ((uint2*)g_Ahi)[i] = ph;
    ((uint2*)g_Alo)[i] = pl;
}

// ---------------- launch 1: mega-prep ----------------------------------------
__global__ void prep_all_kernel(
    const float* __restrict__ W0, const float* __restrict__ W1,
    const float* __restrict__ W2, const float* __restrict__ W3,
    const float* __restrict__ U0, const float* __restrict__ U1,
    const float* __restrict__ U2, const float* __restrict__ U3,
    const float* __restrict__ bi, const float* __restrict__ bf,
    const float* __restrict__ bg, const float* __restrict__ bc)
{
    __shared__ float t[32][33];
    const int bx  = blockIdx.x;
    const int tid = threadIdx.x;
    const int tx  = tid & 31;
    const int ty  = tid >> 5;

    if (bx < 1024) {                     // W transpose -> g_Bhi/g_Blo
        int z = bx >> 8, rem = bx & 255;
        const float* W = (z == 0) ? W0 : (z == 1) ? W1 : (z == 2) ? W2 : W3;
        int n0 = (rem & 15) * 32, k0 = (rem >> 4) * 32;
#pragma unroll
        for (int r = 0; r < 32; r += 8)
            t[ty + r][tx] = W[(size_t)(k0 + ty + r) * NSZ + n0 + tx];
        __syncthreads();
#pragma unroll
        for (int r = 0; r < 32; r += 8) {
            float v = t[tx][ty + r];
            size_t o = (size_t)(z * NSZ + n0 + ty + r) * DSZ + k0 + tx;
            g_Bhi[o] = __float2bfloat16(v);
            g_Blo[o] = __float2bfloat16(bf16res(v));
        }
    } else if (bx < 2048) {              // U transpose -> g_UThi/g_UTlo
        int idx = bx - 1024;
        int z = idx >> 8, rem = idx & 255;
        const float* U = (z == 0) ? U0 : (z == 1) ? U1 : (z == 2) ? U2 : U3;
        int n0 = (rem & 15) * 32, k0 = (rem >> 4) * 32;
#pragma unroll
        for (int r = 0; r < 32; r += 8)
            t[ty + r][tx] = U[(size_t)(k0 + ty + r) * NSZ + n0 + tx];
        __syncthreads();
#pragma unroll
        for (int r = 0; r < 32; r += 8) {
            float v = t[tx][ty + r];
            size_t o = ((size_t)(n0 + ty + r) * 4 + z) * DSZ + k0 + tx;
            g_UThi[o] = __float2bfloat16(v);
            g_UTlo[o] = __float2bfloat16(bf16res(v));
        }
    } else if (bx < 2050) {              // bias concat
        int i = (bx - 2048) * 256 + tid;
        g_biascat[i]           = bi[i];
        g_biascat[NSZ + i]     = bf[i];
        g_biascat[2 * NSZ + i] = bg[i];
        g_biascat[3 * NSZ + i] = bc[i];
    } else {                             // reset h buffers + counters
        int i = (bx - 2050) * 256 + tid;           // 0..8191
        for (int j = i; j < 12288; j += 8192) {
            if (j < 6144) ((uint4*)g_h3H)[j] = make_uint4(0, 0, 0, 0);
            else          ((uint4*)g_h3L)[j - 6144] = make_uint4(0, 0, 0, 0);
        }
        if (i < 1024) g_pcnt[i] = 0;
    }
}

__global__ void wtrans_kernel(const float* __restrict__ W, int rowbase)
{
    __shared__ float t[32][33];
    int tx = threadIdx.x, ty = threadIdx.y;
    int n0 = blockIdx.x * 32, k0 = blockIdx.y * 32;
#pragma unroll
    for (int r = 0; r < 32; r += 8)
        t[ty + r][tx] = W[(size_t)(k0 + ty + r) * NSZ + n0 + tx];
    __syncthreads();
#pragma unroll
    for (int r = 0; r < 32; r += 8) {
        float v = t[tx][ty + r];
        size_t o = (size_t)(rowbase + n0 + ty + r) * DSZ + k0 + tx;
        g_Bhi[o] = __float2bfloat16(v);
        g_Blo[o] = __float2bfloat16(bf16res(v));
    }
}

// ---------------- HMMA GEMM (mma.sync bf16 hi/lo, fp32 accum) ----------------
#define GSM_TOTAL (2 * 65536)

__global__ __launch_bounds__(256, 1) void gemm_mma_kernel(
    const float* __restrict__ bias_ext, float* __restrict__ out_ext, int mode)
{
    extern __shared__ char smem[];
    const uint32_t smem_base = smem_to_u32(smem);
    const int tid  = threadIdx.x;
    const int wid  = tid >> 5;
    const int lane = tid & 31;
    const int wm   = wid & 1;
    const int wn   = wid >> 1;
    const int mbase = blockIdx.y * 128;
    const int nbase = blockIdx.x * 128;

    uint32_t dsts[16];
#pragma unroll
    for (int v = 0; v < 16; v++) {
        int row = (v & 3) * 32 + (tid >> 3);
        uint32_t off = row * 128 + (tid & 7) * 16;
        dsts[v] = (uint32_t)((v >> 2) * 16384) + (off ^ ((off >> 3) & 0x70));
    }

#define ISSUE_CHUNK(KT, BUFOFF) do {                                                 \
    int _kt = (KT);                                                                  \
    uint32_t _bo = (BUFOFF);                                                         \
    _Pragma("unroll")                                                                \
    for (int v = 0; v < 16; v++) {                                                   \
        const __nv_bfloat16* bp = (v < 4) ? g_Ahi : (v < 8) ? g_Alo                  \
                                  : (v < 12) ? g_Bhi : g_Blo;                        \
        int rb = (v < 8) ? mbase : nbase;                                            \
        int row = (v & 3) * 32 + (tid >> 3);                                         \
        CP_ASYNC16(smem_base + _bo + dsts[v],                                        \
                   bp + ((size_t)(rb + row) << 9) + _kt + ((tid & 7) << 3));         \
    }                                                                                \
    CP_COMMIT();                                                                     \
} while (0)

    uint32_t a_rowoff[4], a_swz[4];
#pragma unroll
    for (int mf = 0; mf < 4; mf++) {
        int row = wm * 64 + mf * 16 + (lane & 15);
        a_rowoff[mf] = row * 128;
        a_swz[mf]    = (row & 7) << 4;
    }
    const uint32_t a_cb = (uint32_t)(lane >> 4) * 16;
    uint32_t b_rowoff[4], b_swz[4];
#pragma unroll
    for (int nf = 0; nf < 4; nf++) {
        int row = wn * 32 + nf * 8 + (lane & 7);
        b_rowoff[nf] = row * 128;
        b_swz[nf]    = (row & 7) << 4;
    }
    const uint32_t b_cb = (uint32_t)((lane >> 3) & 1) * 16;

    float acc[4][4][4];
#pragma unroll
    for (int mf = 0; mf < 4; mf++)
#pragma unroll
        for (int nf = 0; nf < 4; nf++)
#pragma unroll
            for (int q = 0; q < 4; q++) acc[mf][nf][q] = 0.f;

    ISSUE_CHUNK(0, 0);

    for (int i = 0; i < 8; i++) {
        if (i < 7) {
            ISSUE_CHUNK((i + 1) * 64, (uint32_t)(((i + 1) & 1) * 65536));
            CP_WAIT(1);
        } else {
            CP_WAIT(0);
        }
        __syncthreads();

        const uint32_t base = smem_base + (uint32_t)((i & 1) * 65536);
#pragma unroll
        for (int k16 = 0; k16 < 4; k16++) {
            const uint32_t kb = (uint32_t)(k16 * 32);
            uint32_t aH[4][4], aL[4][4], bH[4][2], bL[4][2];
#pragma unroll
            for (int mf = 0; mf < 4; mf++) {
                uint32_t co = (kb + a_cb) ^ a_swz[mf];
                ldsm_x4(aH[mf], base + a_rowoff[mf] + co);
                ldsm_x4(aL[mf], base + 16384 + a_rowoff[mf] + co);
            }
#pragma unroll
            for (int nf = 0; nf < 4; nf++) {
                uint32_t co = (kb + b_cb) ^ b_swz[nf];
                ldsm_x2(bH[nf], base + 32768 + b_rowoff[nf] + co);
                ldsm_x2(bL[nf], base + 49152 + b_rowoff[nf] + co);
            }
#pragma unroll
            for (int mf = 0; mf < 4; mf++)
#pragma unroll
                for (int nf = 0; nf < 4; nf++) {
                    mma16816(acc[mf][nf], aH[mf], bH[nf]);
                    mma16816(acc[mf][nf], aH[mf], bL[nf]);
                    mma16816(acc[mf][nf], aL[mf], bH[nf]);
                }
        }
        __syncthreads();
    }

    const float* bias = mode ? bias_ext : g_biascat;
    float* C = mode ? out_ext : g_G;
    const int ncols = mode ? NSZ : NCAT;

#pragma unroll
    for (int mf = 0; mf < 4; mf++) {
#pragma unroll
        for (int h = 0; h < 2; h++) {
            int r = mbase + wm * 64 + mf * 16 + (lane >> 2) + h * 8;
            size_t crow;
            if (mode == 0) {
                int tt = r & (TSZ - 1), bb = r >> 11;
                crow = ((size_t)tt * BSZ + bb) * (size_t)ncols;
            } else {
                int tt = r >> 5, bb = r & 31;
                crow = ((size_t)bb * TSZ + tt) * (size_t)ncols;
            }
#pragma unroll
            for (int nf = 0; nf < 4; nf++) {
                int col = nbase + wn * 32 + nf * 8 + (lane & 3) * 2;
                float2 bv = *(const float2*)&bias[col];
                float2 o;
                o.x = acc[mf][nf][h * 2 + 0] + bv.x;
                o.y = acc[mf][nf][h * 2 + 1] + bv.y;
                if (mode) { o.x = fmaxf(o.x, 0.f); o.y = fmaxf(o.y, 0.f); }
                *(float2*)&C[crow + col] = o;
            }
        }
    }
#undef ISSUE_CHUNK
}

// ---------------- persistent MMA recurrence (batch-group partitioned) --------
// R15 structure; R16 delta: 8 sub-counters per group (4 CTAs each, 128B apart),
// consumers poll all 8 in parallel (lanes 0-7 + __all_sync) -- no flag hop,
// release drain serialization 32x -> 4x.
#define SH 1040
#define RSM_HH 0
#define RSM_HL (8 * SH)
#define RSM_PART (16 * SH)
#define RSM_C (RSM_PART + 9216)
#define RSM_TOTAL (128 * SH)

__global__ __launch_bounds__(512, 1) void lstm_recur_mma()
{
    extern __shared__ char sm[];
    const uint32_t sb = smem_to_u32(sm);
    const int tid  = threadIdx.x;
    const int wid  = tid >> 5;
    const int lane = tid & 31;
    const int ks   = wid & 3;
    const int ms   = wid >> 2;
    const int cta  = blockIdx.x;
    const int bg   = cta >> 5;
    const int ci   = cta & 31;

    // ---- one-time: stage UT slice (64 rows hi + 64 lo), build A-frags ----
#pragma unroll
    for (int q = 0; q < 16; q++) {
        int idx  = q * 512 + tid;
        int half = idx >> 12;
        int rem  = idx & 4095;
        int row  = rem >> 6, col = rem & 63;
        const __nv_bfloat16* src = half ? g_UTlo : g_UThi;
        CP_ASYNC16(sb + half * (64 * SH) + row * SH + col * 16,
                   src + ((size_t)(ci * 64 + row)) * DSZ + col * 8);
    }
    CP_COMMIT();
    CP_WAIT(0);
    __syncthreads();

    uint32_t aH[8][4], aL[8][4];
    {
        uint32_t rbase = sb + (ms * 16 + (lane & 15)) * SH + (lane >> 4) * 16;
#pragma unroll
        for (int j = 0; j < 8; j++) {
            uint32_t co = (uint32_t)(ks * 256 + j * 32);
            ldsm_x4(aH[j], rbase + co);
            ldsm_x4(aL[j], rbase + 64 * SH + co);
        }
    }
    __syncthreads();
    if (tid < 128) ((float*)(sm + RSM_C))[tid] = 0.f;
    __syncthreads();

    const int en = tid & 15;
    const int eb = tid >> 4;                   // valid for tid < 128

    float nxi = 0.f, nxf = 0.f, nxg = 0.f, nxc = 0.f;
    if (tid < 128) {
        size_t gb = (size_t)(bg * 8 + eb) * NCAT + (ci * 16 + en);
        nxi = __ldg(&g_G[gb]);
        nxf = __ldg(&g_G[gb + NSZ]);
        nxg = __ldg(&g_G[gb + 2 * NSZ]);
        nxc = __ldg(&g_G[gb + 3 * NSZ]);
    }

    const int lrow = lane >> 2;
    const uint32_t lcb = (uint32_t)(ks * 256 + (lane & 3) * 64);
    const uint32_t ldH = sb + RSM_HH + (uint32_t)lrow * SH + lcb;
    const uint32_t ldL = sb + RSM_HL + (uint32_t)lrow * SH + lcb;
    const uint32_t hbase = sb + (uint32_t)((lane & 7) * SH)
                         + (uint32_t)(((lane >> 3) & 1) * 16);

    // sub-counter bases: group bg, sub s -> g_pcnt[(bg*8+s)*32]
    int* mycnt = &g_pcnt[(bg * 8 + (ci >> 2)) * 32];
    const int* pollbase = &g_pcnt[(bg * 8 + (lane & 7)) * 32];

    int rbuf = 2, wbuf = 0;
    for (int t = 0; t < TSZ; t++) {
        const float xi = nxi, xf = nxf, xg = nxg, xc = nxc;

        if (wid < 4) {
            // poll all 8 sub-counters in parallel (lanes 0-7)
            {
                const int target = 4 * t;
                int v = (lane < 8) ? ld_acq(pollbase) : 0x40000000;
                while (!__all_sync(0xffffffffu, v >= target)) {
                    if (lane < 8) v = ld_acq(pollbase);
                }
            }
            const char* sH = (const char*)(g_h3H[rbuf] + (bg * 8 + lrow) * NSZ) + lcb;
            const char* sL = (const char*)(g_h3L[rbuf] + (bg * 8 + lrow) * NSZ) + lcb;
#pragma unroll
            for (int i = 0; i < 4; i++) CP_ASYNC16(ldH + 16 * i, sH + 16 * i);
#pragma unroll
            for (int i = 0; i < 4; i++) CP_ASYNC16(ldL + 16 * i, sL + 16 * i);
            CP_COMMIT();
            if (t + 1 < TSZ) {                 // prefetch G(t+1), overlaps loads
                size_t gb = ((size_t)(t + 1) * BSZ + bg * 8 + eb) * (size_t)NCAT
                          + (ci * 16 + en);
                nxi = __ldg(&g_G[gb]);
                nxf = __ldg(&g_G[gb + NSZ]);
                nxg = __ldg(&g_G[gb + 2 * NSZ]);
                nxc = __ldg(&g_G[gb + 3 * NSZ]);
            }
            CP_WAIT(0);
        }
        asm volatile("bar.sync %0, 128;" :: "r"(1 + ks));

        // 3 split accumulators -> RAW chains of 8 instead of 24
        float a0[4] = {0.f, 0.f, 0.f, 0.f};
        float a1[4] = {0.f, 0.f, 0.f, 0.f};
        float a2[4] = {0.f, 0.f, 0.f, 0.f};
#pragma unroll
        for (int j = 0; j < 8; j++) {
            uint32_t co = (uint32_t)(ks * 256 + j * 32);
            uint32_t bH[2], bL[2];
            ldsm_x2(bH, hbase + RSM_HH + co);
            ldsm_x2(bL, hbase + RSM_HL + co);
            mma16816(a0, aH[j], bH);
            mma16816(a1, aH[j], bL);
            mma16816(a2, aL[j], bH);
        }
        {
            float* part = (float*)(sm + RSM_PART);
            int r0 = ms * 16 + (lane >> 2);
            int bc = (lane & 3) * 2;
            part[(ks * 64 + r0) * 9 + bc]         = a0[0] + a1[0] + a2[0];
            part[(ks * 64 + r0) * 9 + bc + 1]     = a0[1] + a1[1] + a2[1];
            part[(ks * 64 + r0 + 8) * 9 + bc]     = a0[2] + a1[2] + a2[2];
            part[(ks * 64 + r0 + 8) * 9 + bc + 1] = a0[3] + a1[3] + a2[3];
        }
        __syncthreads();

        if (tid < 128) {
            const float* part = (const float*)(sm + RSM_PART);
            int m0 = en * 4;
            float s0 = part[m0 * 9 + eb] + part[(64 + m0) * 9 + eb]
                     + part[(128 + m0) * 9 + eb] + part[(192 + m0) * 9 + eb];
            float s1 = part[(m0 + 1) * 9 + eb] + part[(64 + m0 + 1) * 9 + eb]
                     + part[(128 + m0 + 1) * 9 + eb] + part[(192 + m0 + 1) * 9 + eb];
            float s2 = part[(m0 + 2) * 9 + eb] + part[(64 + m0 + 2) * 9 + eb]
                     + part[(128 + m0 + 2) * 9 + eb] + part[(192 + m0 + 2) * 9 + eb];
            float s3 = part[(m0 + 3) * 9 + eb] + part[(64 + m0 + 3) * 9 + eb]
                     + part[(128 + m0 + 3) * 9 + eb] + part[(192 + m0 + 3) * 9 + eb];

            float ig = 1.f / (1.f + __expf(-(s0 + xi)));
            float fg = 1.f / (1.f + __expf(-(s1 + xf)));
            float gg = 1.f / (1.f + __expf(-(s2 + xg)));
            float ct = 1.f - 2.f / (__expf(2.f * (s3 + xc)) + 1.f);

            float* cs = (float*)(sm + RSM_C);
            float c = fg * cs[tid] + ig * ct;
            cs[tid] = c;
            float h = gg * (1.f - 2.f / (__expf(2.f * c) + 1.f));

            int n = ci * 16 + en;
            int brow = bg * 8 + eb;
            __nv_bfloat16 hh = __float2bfloat16(h);
            __nv_bfloat16 hl = __float2bfloat16(h - __bfloat162float(hh));
            // exchange stores first (fence-covered), release, then history
            g_h3H[wbuf][brow * NSZ + n] = hh;
            g_h3L[wbuf][brow * NSZ + n] = hl;
            asm volatile("bar.sync 5, 128;");
            if (tid == 0) {
                __threadfence();
                atomicAdd(mycnt, 1);           // return unused -> REDG
            }
            size_t ar = ((size_t)t * BSZ + brow) * (size_t)NSZ + n;
            g_Ahi[ar] = hh;                    // consumed only after kernel exit
            g_Alo[ar] = hl;
        }

        rbuf = (rbuf == 2) ? 0 : rbuf + 1;
        wbuf = (wbuf == 2) ? 0 : wbuf + 1;
    }
}

// ---------------- launcher ---------------------------------------------------
extern "C" void kernel_launch(void* const* d_in, const int* in_sizes, int n_in,
                              void* d_out, int out_size)
{
    (void)in_sizes; (void)n_in; (void)out_size;
    const float* x   = (const float*)d_in[0];
    const float* W_i = (const float*)d_in[1];
    const float* U_i = (const float*)d_in[2];
    const float* W_f = (const float*)d_in[3];
    const float* U_f = (const float*)d_in[4];
    const float* W_g = (const float*)d_in[5];
    const float* U_g = (const float*)d_in[6];
    const float* W_c = (const float*)d_in[7];
    const float* U_c = (const float*)d_in[8];
    const float* W_o = (const float*)d_in[9];
    const float* b_i = (const float*)d_in[10];
    const float* b_f = (const float*)d_in[11];
    const float* b_g = (const float*)d_in[12];
    const float* b_c = (const float*)d_in[13];
    const float* b_o = (const float*)d_in[14];
    float* out = (float*)d_out;

    cudaFuncSetAttribute(lstm_recur_mma,
                         cudaFuncAttributeMaxDynamicSharedMemorySize, RSM_TOTAL);
    cudaFuncSetAttribute(gemm_mma_kernel,
                         cudaFuncAttributeMaxDynamicSharedMemorySize, GSM_TOTAL);

    cvt_x_kernel<<<(int)(((size_t)MROWS * DSZ / 4) / 256), 256>>>(x);
    prep_all_kernel<<<2082, 256>>>(W_i, W_f, W_g, W_c, U_i, U_f, U_g, U_c,
                                   b_i, b_f, b_g, b_c);
    gemm_mma_kernel<<<dim3(NCAT / 128, MROWS / 128), 256, GSM_TOTAL>>>(nullptr, nullptr, 0);
    lstm_recur_mma<<<128, 512, RSM_TOTAL>>>();
    {
        dim3 g(16, 16), b(32, 8);
        wtrans_kernel<<<g, b>>>(W_o, 0);
    }
    gemm_mma_kernel<<<dim3(NSZ / 128, MROWS / 128), 256, GSM_TOTAL>>>(b_o, out, 1);
}

// round 17
// speedup vs baseline: 1.2937x; 1.0215x over previous
#include <cuda_runtime.h>
#include <cuda_bf16.h>
#include <cstdint>
#include <cstddef>

#define BSZ 32
#define TSZ 2048
#define DSZ 512
#define NSZ 512
#define MROWS (BSZ * TSZ)      // 65536
#define NCAT  (4 * NSZ)        // 2048

// ---------------- device scratch (allocation-free: __device__ globals) -------
__device__ float  g_G[(size_t)TSZ * BSZ * NCAT];         // 512 MB  [t][b][gate*512+n]
__device__ __nv_bfloat16 g_Ahi[(size_t)MROWS * DSZ];     // 64 MB (x, then h history)
__device__ __nv_bfloat16 g_Alo[(size_t)MROWS * DSZ];     // 64 MB
__device__ __nv_bfloat16 g_Bhi[(size_t)NCAT * DSZ];      // 2 MB   [n][k] (W^T)
__device__ __nv_bfloat16 g_Blo[(size_t)NCAT * DSZ];      // 2 MB
__device__ __nv_bfloat16 g_UThi[(size_t)NCAT * DSZ];     // 2 MB   [n*4+gate][k]
__device__ __nv_bfloat16 g_UTlo[(size_t)NCAT * DSZ];     // 2 MB
__device__ __nv_bfloat16 g_h3H[3][BSZ * NSZ];            // depth-3 h (hi)
__device__ __nv_bfloat16 g_h3L[3][BSZ * NSZ];            // depth-3 h (lo)
__device__ float  g_biascat[NCAT];
__device__ int    g_pcnt[4 * 32 * 32];                   // per-CTA counters, 128B apart

// ---------------- PTX helpers (baseline PTX: sm_80+ features only) ----------
__device__ __forceinline__ uint32_t smem_to_u32(const void* p) {
    uint32_t a;
    asm("{ .reg .u64 t; cvta.to.shared.u64 t, %1; cvt.u32.u64 %0, t; }" : "=r"(a) : "l"(p));
    return a;
}
#define CP_ASYNC16(dst, src) \
    asm volatile("cp.async.cg.shared.global [%0], [%1], 16;" :: "r"(dst), "l"(src))
#define CP_COMMIT() asm volatile("cp.async.commit_group;" ::: "memory")
#define CP_WAIT(n)  asm volatile("cp.async.wait_group %0;" :: "n"(n) : "memory")

__device__ __forceinline__ void ldsm_x4(uint32_t* r, uint32_t addr) {
    asm volatile("ldmatrix.sync.aligned.m8n8.x4.shared.b16 {%0,%1,%2,%3}, [%4];"
                 : "=r"(r[0]), "=r"(r[1]), "=r"(r[2]), "=r"(r[3]) : "r"(addr));
}
__device__ __forceinline__ void ldsm_x2(uint32_t* r, uint32_t addr) {
    asm volatile("ldmatrix.sync.aligned.m8n8.x2.shared.b16 {%0,%1}, [%2];"
                 : "=r"(r[0]), "=r"(r[1]) : "r"(addr));
}
__device__ __forceinline__ void mma16816(float* c, const uint32_t* a, const uint32_t* b) {
    asm volatile("mma.sync.aligned.m16n8k16.row.col.f32.bf16.bf16.f32 "
                 "{%0,%1,%2,%3}, {%4,%5,%6,%7}, {%8,%9}, {%0,%1,%2,%3};"
                 : "+f"(c[0]), "+f"(c[1]), "+f"(c[2]), "+f"(c[3])
                 : "r"(a[0]), "r"(a[1]), "r"(a[2]), "r"(a[3]), "r"(b[0]), "r"(b[1]));
}
__device__ __forceinline__ int ld_acq(const int* p) {
    int v;
    asm volatile("ld.acquire.gpu.global.b32 %0, [%1];" : "=r"(v) : "l"(p) : "memory");
    return v;
}
__device__ __forceinline__ void red_release_add(int* p, int v) {
    asm volatile("red.release.gpu.global.add.s32 [%0], %1;" :: "l"(p), "r"(v) : "memory");
}

// ---------------- conversion helpers -----------------------------------------
__device__ __forceinline__ unsigned bf16pack2(float a, float b)
{
    return (unsigned)__bfloat16_as_ushort(__float2bfloat16(a)) |
           ((unsigned)__bfloat16_as_ushort(__float2bfloat16(b)) << 16);
}
__device__ __forceinline__ float bf16res(float a)
{
    return a - __bfloat162float(__float2bfloat16(a));
}

// ---------------- launch 0: x -> bf16 hi/lo ----------------------------------
__global__ void cvt_x_kernel(const float* __restrict__ src)
{
    size_t i = (size_t)blockIdx.x * 256 + threadIdx.x;
    float4 v = ((const float4*)src)[i];
    uint2 ph, pl;
    ph.x = bf16pack2(v.x, v.y);
    ph.y = bf16pack2(v.z, v.w);
    pl.x = bf16pack2(bf16res(v.x), bf16res(v.y));
    pl.y = bf16pack2(bf16res(v.z), bf16res(v.w));
    ((uint2*)g_Ahi)[i] = ph;
    ((uint2*)g_Alo)[i] = pl;
}

// ---------------- launch 1: mega-prep ----------------------------------------
__global__ void prep_all_kernel(
    const float* __restrict__ W0, const float* __restrict__ W1,
    const float* __restrict__ W2, const float* __restrict__ W3,
    const float* __restrict__ U0, const float* __restrict__ U1,
    const float* __restrict__ U2, const float* __restrict__ U3,
    const float* __restrict__ bi, const float* __restrict__ bf,
    const float* __restrict__ bg, const float* __restrict__ bc)
{
    __shared__ float t[32][33];
    const int bx  = blockIdx.x;
    const int tid = threadIdx.x;
    const int tx  = tid & 31;
    const int ty  = tid >> 5;

    if (bx < 1024) {                     // W transpose -> g_Bhi/g_Blo
        int z = bx >> 8, rem = bx & 255;
        const float* W = (z == 0) ? W0 : (z == 1) ? W1 : (z == 2) ? W2 : W3;
        int n0 = (rem & 15) * 32, k0 = (rem >> 4) * 32;
#pragma unroll
        for (int r = 0; r < 32; r += 8)
            t[ty + r][tx] = W[(size_t)(k0 + ty + r) * NSZ + n0 + tx];
        __syncthreads();
#pragma unroll
        for (int r = 0; r < 32; r += 8) {
            float v = t[tx][ty + r];
            size_t o = (size_t)(z * NSZ + n0 + ty + r) * DSZ + k0 + tx;
            g_Bhi[o] = __float2bfloat16(v);
            g_Blo[o] = __float2bfloat16(bf16res(v));
        }
    } else if (bx < 2048) {              // U transpose -> g_UThi/g_UTlo
        int idx = bx - 1024;
        int z = idx >> 8, rem = idx & 255;
        const float* U = (z == 0) ? U0 : (z == 1) ? U1 : (z == 2) ? U2 : U3;
        int n0 = (rem & 15) * 32, k0 = (rem >> 4) * 32;
#pragma unroll
        for (int r = 0; r < 32; r += 8)
            t[ty + r][tx] = U[(size_t)(k0 + ty + r) * NSZ + n0 + tx];
        __syncthreads();
#pragma unroll
        for (int r = 0; r < 32; r += 8) {
            float v = t[tx][ty + r];
            size_t o = ((size_t)(n0 + ty + r) * 4 + z) * DSZ + k0 + tx;
            g_UThi[o] = __float2bfloat16(v);
            g_UTlo[o] = __float2bfloat16(bf16res(v));
        }
    } else if (bx < 2050) {              // bias concat
        int i = (bx - 2048) * 256 + tid;
        g_biascat[i]           = bi[i];
        g_biascat[NSZ + i]     = bf[i];
        g_biascat[2 * NSZ + i] = bg[i];
        g_biascat[3 * NSZ + i] = bc[i];
    } else {                             // reset h buffers + counters
        int i = (bx - 2050) * 256 + tid;           // 0..1023
        for (int j = i; j < 12288; j += 1024) {
            if (j < 6144) ((uint4*)g_h3H)[j] = make_uint4(0, 0, 0, 0);
            else          ((uint4*)g_h3L)[j - 6144] = make_uint4(0, 0, 0, 0);
        }
        for (int j = i; j < 4096; j += 1024) g_pcnt[j] = 0;
    }
}

__global__ void wtrans_kernel(const float* __restrict__ W, int rowbase)
{
    __shared__ float t[32][33];
    int tx = threadIdx.x, ty = threadIdx.y;
    int n0 = blockIdx.x * 32, k0 = blockIdx.y * 32;
#pragma unroll
    for (int r = 0; r < 32; r += 8)
        t[ty + r][tx] = W[(size_t)(k0 + ty + r) * NSZ + n0 + tx];
    __syncthreads();
#pragma unroll
    for (int r = 0; r < 32; r += 8) {
        float v = t[tx][ty + r];
        size_t o = (size_t)(rowbase + n0 + ty + r) * DSZ + k0 + tx;
        g_Bhi[o] = __float2bfloat16(v);
        g_Blo[o] = __float2bfloat16(bf16res(v));
    }
}

// ---------------- HMMA GEMM (mma.sync bf16 hi/lo, fp32 accum) ----------------
#define GSM_TOTAL (2 * 65536)

__global__ __launch_bounds__(256, 1) void gemm_mma_kernel(
    const float* __restrict__ bias_ext, float* __restrict__ out_ext, int mode)
{
    extern __shared__ char smem[];
    const uint32_t smem_base = smem_to_u32(smem);
    const int tid  = threadIdx.x;
    const int wid  = tid >> 5;
    const int lane = tid & 31;
    const int wm   = wid & 1;
    const int wn   = wid >> 1;
    const int mbase = blockIdx.y * 128;
    const int nbase = blockIdx.x * 128;

    uint32_t dsts[16];
#pragma unroll
    for (int v = 0; v < 16; v++) {
        int row = (v & 3) * 32 + (tid >> 3);
        uint32_t off = row * 128 + (tid & 7) * 16;
        dsts[v] = (uint32_t)((v >> 2) * 16384) + (off ^ ((off >> 3) & 0x70));
    }

#define ISSUE_CHUNK(KT, BUFOFF) do {                                                 \
    int _kt = (KT);                                                                  \
    uint32_t _bo = (BUFOFF);                                                         \
    _Pragma("unroll")                                                                \
    for (int v = 0; v < 16; v++) {                                                   \
        const __nv_bfloat16* bp = (v < 4) ? g_Ahi : (v < 8) ? g_Alo                  \
                                  : (v < 12) ? g_Bhi : g_Blo;                        \
        int rb = (v < 8) ? mbase : nbase;                                            \
        int row = (v & 3) * 32 + (tid >> 3);                                         \
        CP_ASYNC16(smem_base + _bo + dsts[v],                                        \
                   bp + ((size_t)(rb + row) << 9) + _kt + ((tid & 7) << 3));         \
    }                                                                                \
    CP_COMMIT();                                                                     \
} while (0)

    uint32_t a_rowoff[4], a_swz[4];
#pragma unroll
    for (int mf = 0; mf < 4; mf++) {
        int row = wm * 64 + mf * 16 + (lane & 15);
        a_rowoff[mf] = row * 128;
        a_swz[mf]    = (row & 7) << 4;
    }
    const uint32_t a_cb = (uint32_t)(lane >> 4) * 16;
    uint32_t b_rowoff[4], b_swz[4];
#pragma unroll
    for (int nf = 0; nf < 4; nf++) {
        int row = wn * 32 + nf * 8 + (lane & 7);
        b_rowoff[nf] = row * 128;
        b_swz[nf]    = (row & 7) << 4;
    }
    const uint32_t b_cb = (uint32_t)((lane >> 3) & 1) * 16;

    float acc[4][4][4];
#pragma unroll
    for (int mf = 0; mf < 4; mf++)
#pragma unroll
        for (int nf = 0; nf < 4; nf++)
#pragma unroll
            for (int q = 0; q < 4; q++) acc[mf][nf][q] = 0.f;

    ISSUE_CHUNK(0, 0);

    for (int i = 0; i < 8; i++) {
        if (i < 7) {
            ISSUE_CHUNK((i + 1) * 64, (uint32_t)(((i + 1) & 1) * 65536));
            CP_WAIT(1);
        } else {
            CP_WAIT(0);
        }
        __syncthreads();

        const uint32_t base = smem_base + (uint32_t)((i & 1) * 65536);
#pragma unroll
        for (int k16 = 0; k16 < 4; k16++) {
            const uint32_t kb = (uint32_t)(k16 * 32);
            uint32_t aH[4][4], aL[4][4], bH[4][2], bL[4][2];
#pragma unroll
            for (int mf = 0; mf < 4; mf++) {
                uint32_t co = (kb + a_cb) ^ a_swz[mf];
                ldsm_x4(aH[mf], base + a_rowoff[mf] + co);
                ldsm_x4(aL[mf], base + 16384 + a_rowoff[mf] + co);
            }
#pragma unroll
            for (int nf = 0; nf < 4; nf++) {
                uint32_t co = (kb + b_cb) ^ b_swz[nf];
                ldsm_x2(bH[nf], base + 32768 + b_rowoff[nf] + co);
                ldsm_x2(bL[nf], base + 49152 + b_rowoff[nf] + co);
            }
#pragma unroll
            for (int mf = 0; mf < 4; mf++)
#pragma unroll
                for (int nf = 0; nf < 4; nf++) {
                    mma16816(acc[mf][nf], aH[mf], bH[nf]);
                    mma16816(acc[mf][nf], aH[mf], bL[nf]);
                    mma16816(acc[mf][nf], aL[mf], bH[nf]);
                }
        }
        __syncthreads();
    }

    const float* bias = mode ? bias_ext : g_biascat;
    float* C = mode ? out_ext : g_G;
    const int ncols = mode ? NSZ : NCAT;

#pragma unroll
    for (int mf = 0; mf < 4; mf++) {
#pragma unroll
        for (int h = 0; h < 2; h++) {
            int r = mbase + wm * 64 + mf * 16 + (lane >> 2) + h * 8;
            size_t crow;
            if (mode == 0) {
                int tt = r & (TSZ - 1), bb = r >> 11;
                crow = ((size_t)tt * BSZ + bb) * (size_t)ncols;
            } else {
                int tt = r >> 5, bb = r & 31;
                crow = ((size_t)bb * TSZ + tt) * (size_t)ncols;
            }
#pragma unroll
            for (int nf = 0; nf < 4; nf++) {
                int col = nbase + wn * 32 + nf * 8 + (lane & 3) * 2;
                float2 bv = *(const float2*)&bias[col];
                float2 o;
                o.x = acc[mf][nf][h * 2 + 0] + bv.x;
                o.y = acc[mf][nf][h * 2 + 1] + bv.y;
                if (mode) { o.x = fmaxf(o.x, 0.f); o.y = fmaxf(o.y, 0.f); }
                *(float2*)&C[crow + col] = o;
            }
        }
    }
#undef ISSUE_CHUNK
}

// ---------------- persistent MMA recurrence (batch-group partitioned) --------
// R16 structure; R17 deltas:
//  - epilogue moved to warps 12-15 (tid>=384) so loader warps 0-3 overlap the
//    next step's poll with the epilogue,
//  - per-CTA counters (fan-in 1), loaders poll 32 counters across lanes,
//  - release via red.release (no separate membar).
#define SH 1040
#define RSM_HH 0
#define RSM_HL (8 * SH)
#define RSM_PART (16 * SH)
#define RSM_C (RSM_PART + 9216)
#define RSM_TOTAL (128 * SH)

__global__ __launch_bounds__(512, 1) void lstm_recur_mma()
{
    extern __shared__ char sm[];
    const uint32_t sb = smem_to_u32(sm);
    const int tid  = threadIdx.x;
    const int wid  = tid >> 5;
    const int lane = tid & 31;
    const int ks   = wid & 3;
    const int ms   = wid >> 2;
    const int cta  = blockIdx.x;
    const int bg   = cta >> 5;
    const int ci   = cta & 31;

    // ---- one-time: stage UT slice (64 rows hi + 64 lo), build A-frags ----
#pragma unroll
    for (int q = 0; q < 16; q++) {
        int idx  = q * 512 + tid;
        int half = idx >> 12;
        int rem  = idx & 4095;
        int row  = rem >> 6, col = rem & 63;
        const __nv_bfloat16* src = half ? g_UTlo : g_UThi;
        CP_ASYNC16(sb + half * (64 * SH) + row * SH + col * 16,
                   src + ((size_t)(ci * 64 + row)) * DSZ + col * 8);
    }
    CP_COMMIT();
    CP_WAIT(0);
    __syncthreads();

    uint32_t aH[8][4], aL[8][4];
    {
        uint32_t rbase = sb + (ms * 16 + (lane & 15)) * SH + (lane >> 4) * 16;
#pragma unroll
        for (int j = 0; j < 8; j++) {
            uint32_t co = (uint32_t)(ks * 256 + j * 32);
            ldsm_x4(aH[j], rbase + co);
            ldsm_x4(aL[j], rbase + 64 * SH + co);
        }
    }
    __syncthreads();
    if (tid >= 384) ((float*)(sm + RSM_C))[tid - 384] = 0.f;
    __syncthreads();

    // epilogue lane mapping (warps 12-15): etid in [0,128)
    const int etid = tid - 384;
    const int en = etid & 15;
    const int eb = etid >> 4;                  // valid for tid >= 384

    float nxi = 0.f, nxf = 0.f, nxg = 0.f, nxc = 0.f;
    if (tid >= 384) {
        size_t gb = (size_t)(bg * 8 + eb) * NCAT + (ci * 16 + en);
        nxi = __ldg(&g_G[gb]);
        nxf = __ldg(&g_G[gb + NSZ]);
        nxg = __ldg(&g_G[gb + 2 * NSZ]);
        nxc = __ldg(&g_G[gb + 3 * NSZ]);
    }

    const int lrow = lane >> 2;
    const uint32_t lcb = (uint32_t)(ks * 256 + (lane & 3) * 64);
    const uint32_t ldH = sb + RSM_HH + (uint32_t)lrow * SH + lcb;
    const uint32_t ldL = sb + RSM_HL + (uint32_t)lrow * SH + lcb;
    const uint32_t hbase = sb + (uint32_t)((lane & 7) * SH)
                         + (uint32_t)(((lane >> 3) & 1) * 16);

    // per-CTA counter; loaders poll all 32 counters of the group across lanes
    int* mycnt = &g_pcnt[(bg * 32 + ci) * 32];
    const int* pollp = &g_pcnt[(bg * 32 + lane) * 32];

    int rbuf = 2, wbuf = 0;
    for (int t = 0; t < TSZ; t++) {
        const float xi = nxi, xf = nxf, xg = nxg, xc = nxc;

        if (wid < 4) {
            // wait until ALL 32 CTAs of the group completed step t-1
            {
                int v = ld_acq(pollp);
                while (!__all_sync(0xffffffffu, v >= t)) v = ld_acq(pollp);
            }
            const char* sH = (const char*)(g_h3H[rbuf] + (bg * 8 + lrow) * NSZ) + lcb;
            const char* sL = (const char*)(g_h3L[rbuf] + (bg * 8 + lrow) * NSZ) + lcb;
#pragma unroll
            for (int i = 0; i < 4; i++) CP_ASYNC16(ldH + 16 * i, sH + 16 * i);
#pragma unroll
            for (int i = 0; i < 4; i++) CP_ASYNC16(ldL + 16 * i, sL + 16 * i);
            CP_COMMIT();
            CP_WAIT(0);
        }
        asm volatile("bar.sync %0, 128;" :: "r"(1 + ks));

        // 3 split accumulators -> RAW chains of 8
        float a0[4] = {0.f, 0.f, 0.f, 0.f};
        float a1[4] = {0.f, 0.f, 0.f, 0.f};
        float a2[4] = {0.f, 0.f, 0.f, 0.f};
#pragma unroll
        for (int j = 0; j < 8; j++) {
            uint32_t co = (uint32_t)(ks * 256 + j * 32);
            uint32_t bH[2], bL[2];
            ldsm_x2(bH, hbase + RSM_HH + co);
            ldsm_x2(bL, hbase + RSM_HL + co);
            mma16816(a0, aH[j], bH);
            mma16816(a1, aH[j], bL);
            mma16816(a2, aL[j], bH);
        }
        {
            float* part = (float*)(sm + RSM_PART);
            int r0 = ms * 16 + (lane >> 2);
            int bc = (lane & 3) * 2;
            part[(ks * 64 + r0) * 9 + bc]         = a0[0] + a1[0] + a2[0];
            part[(ks * 64 + r0) * 9 + bc + 1]     = a0[1] + a1[1] + a2[1];
            part[(ks * 64 + r0 + 8) * 9 + bc]     = a0[2] + a1[2] + a2[2];
            part[(ks * 64 + r0 + 8) * 9 + bc + 1] = a0[3] + a1[3] + a2[3];
        }
        __syncthreads();

        // epilogue on warps 12-15; loaders (0-3) immediately loop to polling
        if (tid >= 384) {
            // prefetch G(t+1) first (latency overlapped with reduce)
            if (t + 1 < TSZ) {
                size_t gb = ((size_t)(t + 1) * BSZ + bg * 8 + eb) * (size_t)NCAT
                          + (ci * 16 + en);
                nxi = __ldg(&g_G[gb]);
                nxf = __ldg(&g_G[gb + NSZ]);
                nxg = __ldg(&g_G[gb + 2 * NSZ]);
                nxc = __ldg(&g_G[gb + 3 * NSZ]);
            }

            const float* part = (const float*)(sm + RSM_PART);
            int m0 = en * 4;
            float s0 = part[m0 * 9 + eb] + part[(64 + m0) * 9 + eb]
                     + part[(128 + m0) * 9 + eb] + part[(192 + m0) * 9 + eb];
            float s1 = part[(m0 + 1) * 9 + eb] + part[(64 + m0 + 1) * 9 + eb]
                     + part[(128 + m0 + 1) * 9 + eb] + part[(192 + m0 + 1) * 9 + eb];
            float s2 = part[(m0 + 2) * 9 + eb] + part[(64 + m0 + 2) * 9 + eb]
                     + part[(128 + m0 + 2) * 9 + eb] + part[(192 + m0 + 2) * 9 + eb];
            float s3 = part[(m0 + 3) * 9 + eb] + part[(64 + m0 + 3) * 9 + eb]
                     + part[(128 + m0 + 3) * 9 + eb] + part[(192 + m0 + 3) * 9 + eb];

            float ig = 1.f / (1.f + __expf(-(s0 + xi)));
            float fg = 1.f / (1.f + __expf(-(s1 + xf)));
            float gg = 1.f / (1.f + __expf(-(s2 + xg)));
            float ct = 1.f - 2.f / (__expf(2.f * (s3 + xc)) + 1.f);

            float* cs = (float*)(sm + RSM_C);
            float c = fg * cs[etid] + ig * ct;
            cs[etid] = c;
            float h = gg * (1.f - 2.f / (__expf(2.f * c) + 1.f));

            int n = ci * 16 + en;
            int brow = bg * 8 + eb;
            __nv_bfloat16 hh = __float2bfloat16(h);
            __nv_bfloat16 hl = __float2bfloat16(h - __bfloat162float(hh));
            g_h3H[wbuf][brow * NSZ + n] = hh;
            g_h3L[wbuf][brow * NSZ + n] = hl;
            asm volatile("bar.sync 5, 128;");
            if (etid == 0) red_release_add(mycnt, 1);
            size_t ar = ((size_t)t * BSZ + brow) * (size_t)NSZ + n;
            g_Ahi[ar] = hh;                    // consumed only after kernel exit
            g_Alo[ar] = hl;
        }

        rbuf = (rbuf == 2) ? 0 : rbuf + 1;
        wbuf = (wbuf == 2) ? 0 : wbuf + 1;
    }
}

// ---------------- launcher ---------------------------------------------------
extern "C" void kernel_launch(void* const* d_in, const int* in_sizes, int n_in,
                              void* d_out, int out_size)
{
    (void)in_sizes; (void)n_in; (void)out_size;
    const float* x   = (const float*)d_in[0];
    const float* W_i = (const float*)d_in[1];
    const float* U_i = (const float*)d_in[2];
    const float* W_f = (const float*)d_in[3];
    const float* U_f = (const float*)d_in[4];
    const float* W_g = (const float*)d_in[5];
    const float* U_g = (const float*)d_in[6];
    const float* W_c = (const float*)d_in[7];
    const float* U_c = (const float*)d_in[8];
    const float* W_o = (const float*)d_in[9];
    const float* b_i = (const float*)d_in[10];
    const float* b_f = (const float*)d_in[11];
    const float* b_g = (const float*)d_in[12];
    const float* b_c = (const float*)d_in[13];
    const float* b_o = (const float*)d_in[14];
    float* out = (float*)d_out;

    cudaFuncSetAttribute(lstm_recur_mma,
                         cudaFuncAttributeMaxDynamicSharedMemorySize, RSM_TOTAL);
    cudaFuncSetAttribute(gemm_mma_kernel,
                         cudaFuncAttributeMaxDynamicSharedMemorySize, GSM_TOTAL);

    cvt_x_kernel<<<(int)(((size_t)MROWS * DSZ / 4) / 256), 256>>>(x);
    prep_all_kernel<<<2054, 256>>>(W_i, W_f, W_g, W_c, U_i, U_f, U_g, U_c,
                                   b_i, b_f, b_g, b_c);
    gemm_mma_kernel<<<dim3(NCAT / 128, MROWS / 128), 256, GSM_TOTAL>>>(nullptr, nullptr, 0);
    lstm_recur_mma<<<128, 512, RSM_TOTAL>>>();
    {
        dim3 g(16, 16), b(32, 8);
        wtrans_kernel<<<g, b>>>(W_o, 0);
    }
    gemm_mma_kernel<<<dim3(NSZ / 128, MROWS / 128), 256, GSM_TOTAL>>>(b_o, out, 1);
}